// round 3
// baseline (speedup 1.0000x reference)
#include <cuda_runtime.h>
#include <math.h>

// ---------------- problem constants ----------------
#define S_TOT  9616        // total sequence
#define RAZOR  8320        // (T-1)*H*W image tokens (rotated order: frames 1..8 first)
#define PF     1040        // tokens per frame
#define ROT    8576        // RAZOR + text_len : rotation pivot
#define NH     2
#define HD     128
#define PRE    2048        // main attention band half-width
#define WIN    301         // ratio mask window: |i-j| <= 301 is "in window"
#define BM     64
#define BN     64
#define NBLK   151         // ceil(9616/64)
#define SCALE  0.08838834764831845f   // 1/sqrt(128)

// rotated index -> original index
__device__ __forceinline__ int orig_idx(int r) { return r < ROT ? r + PF : r - ROT; }

// smem layout (floats)
#define QS_OFF 0
#define KS_OFF (BM*HD)                   // ks stride 132 (bank-conflict pad)
#define VS_OFF (KS_OFF + BN*132)
#define PS_OFF (VS_OFF + BN*HD)          // ps stride 65
#define SMEM_FLOATS (PS_OFF + BM*65)
#define SMEM_BYTES  (SMEM_FLOATS * 4)

// ---------------- main banded flash attention ----------------
__global__ __launch_bounds__(256)
void attn_kernel(const float* __restrict__ Q, const float* __restrict__ K,
                 const float* __restrict__ V, float* __restrict__ O)
{
    extern __shared__ float sm[];
    float* qs = sm + QS_OFF;   // [64][128]
    float* ks = sm + KS_OFF;   // [64][132]
    float* vs = sm + VS_OFF;   // [64][128]
    float* ps = sm + PS_OFF;   // [64][65]

    const int tile = blockIdx.x;
    const int head = blockIdx.y;
    const int r0   = tile * BM;
    const int tid  = threadIdx.x;
    const int tx   = tid & 15;
    const int ty   = tid >> 4;
    const int warp = tid >> 5;
    const int lane = tid & 31;

    // ---- load Q tile (rows r0..r0+63, rotated) ----
#pragma unroll
    for (int i = 0; i < 8; i++) {
        int row = warp * 8 + i;
        int r   = r0 + row;
        int gr  = orig_idx(min(r, S_TOT - 1));
        float4 v = *(const float4*)(Q + ((size_t)gr * NH + head) * HD + lane * 4);
        *(float4*)(qs + row * HD + lane * 4) = v;
    }
    __syncthreads();

    float  m_i[4], l_i[4];
    float4 acc_o[4][2];
#pragma unroll
    for (int i = 0; i < 4; i++) {
        m_i[i] = -INFINITY; l_i[i] = 0.f;
        acc_o[i][0] = make_float4(0.f, 0.f, 0.f, 0.f);
        acc_o[i][1] = make_float4(0.f, 0.f, 0.f, 0.f);
    }

    const bool in_razor = (r0 < RAZOR);   // tiles 0..129 (boundary 8320 = 130*64)
    int nseg, seg_lo[2], seg_hi[2];
    if (in_razor) {
        seg_lo[0] = max(0, tile - 32);  seg_hi[0] = min(130, tile + 33); // band blocks
        seg_lo[1] = 130;                seg_hi[1] = NBLK;                // tail blocks
        nseg = 2;
    } else {
        seg_lo[0] = 0; seg_hi[0] = NBLK; nseg = 1;
    }

    for (int seg = 0; seg < nseg; seg++)
    for (int blk = seg_lo[seg]; blk < seg_hi[seg]; blk++) {
        const int c0 = blk * BN;

        // ---- load K,V block ----
#pragma unroll
        for (int i = 0; i < 8; i++) {
            int row = warp * 8 + i;
            int c   = min(c0 + row, S_TOT - 1);
            int gc  = orig_idx(c);
            const float* kp = K + ((size_t)gc * NH + head) * HD + lane * 4;
            const float* vp = V + ((size_t)gc * NH + head) * HD + lane * 4;
            float4 kv = *(const float4*)kp;
            float4 vv = *(const float4*)vp;
            *(float4*)(ks + row * 132 + lane * 4) = kv;
            *(float4*)(vs + row * HD  + lane * 4) = vv;
        }
        __syncthreads();

        // ---- scores: 64x64 = (4x4 per thread), float4 over k-dim ----
        float acc[4][4];
#pragma unroll
        for (int i = 0; i < 4; i++)
#pragma unroll
            for (int j = 0; j < 4; j++) acc[i][j] = 0.f;

#pragma unroll 4
        for (int kk = 0; kk < HD; kk += 4) {
            float4 a[4], b[4];
#pragma unroll
            for (int i = 0; i < 4; i++) a[i] = *(float4*)(qs + (ty + 16 * i) * HD  + kk);
#pragma unroll
            for (int j = 0; j < 4; j++) b[j] = *(float4*)(ks + (tx + 16 * j) * 132 + kk);
#pragma unroll
            for (int i = 0; i < 4; i++)
#pragma unroll
                for (int j = 0; j < 4; j++)
                    acc[i][j] += a[i].x * b[j].x + a[i].y * b[j].y
                               + a[i].z * b[j].z + a[i].w * b[j].w;
        }

        // ---- mask + online softmax ----
#pragma unroll
        for (int i = 0; i < 4; i++) {
            int r = r0 + ty + 16 * i;
            float s[4];
            float bm = -INFINITY;
#pragma unroll
            for (int j = 0; j < 4; j++) {
                int c = c0 + tx + 16 * j;
                bool ok;
                if (in_razor) ok = (c >= RAZOR) ? (c < S_TOT) : (abs(r - c) <= PRE);
                else          ok = (c < S_TOT);
                s[j] = ok ? acc[i][j] * SCALE : -INFINITY;
                bm = fmaxf(bm, s[j]);
            }
#pragma unroll
            for (int off = 8; off >= 1; off >>= 1)
                bm = fmaxf(bm, __shfl_xor_sync(0xffffffffu, bm, off));
            float m_new = fmaxf(m_i[i], bm);       // finite: every block has >=1 valid col
            float sc = __expf(m_i[i] - m_new);     // 0 on first block
            l_i[i] *= sc;
            acc_o[i][0].x *= sc; acc_o[i][0].y *= sc; acc_o[i][0].z *= sc; acc_o[i][0].w *= sc;
            acc_o[i][1].x *= sc; acc_o[i][1].y *= sc; acc_o[i][1].z *= sc; acc_o[i][1].w *= sc;
            float psum = 0.f;
#pragma unroll
            for (int j = 0; j < 4; j++) {
                float p = __expf(s[j] - m_new);
                psum += p;
                ps[(ty + 16 * i) * 65 + tx + 16 * j] = p;
            }
            l_i[i] += psum;
            m_i[i]  = m_new;
        }
        __syncthreads();

        // ---- PV: acc_o += P(64x64) @ V(64x128) ----
#pragma unroll 4
        for (int c = 0; c < BN; c++) {
            float4 v0 = *(float4*)(vs + c * HD +      tx * 4);
            float4 v1 = *(float4*)(vs + c * HD + 64 + tx * 4);
#pragma unroll
            for (int i = 0; i < 4; i++) {
                float p = ps[(ty + 16 * i) * 65 + c];
                acc_o[i][0].x += p * v0.x; acc_o[i][0].y += p * v0.y;
                acc_o[i][0].z += p * v0.z; acc_o[i][0].w += p * v0.w;
                acc_o[i][1].x += p * v1.x; acc_o[i][1].y += p * v1.y;
                acc_o[i][1].z += p * v1.z; acc_o[i][1].w += p * v1.w;
            }
        }
        __syncthreads();
    }

    // ---- finalize: reduce l over 16 tx lanes, write rotated-back ----
#pragma unroll
    for (int i = 0; i < 4; i++) {
        float l = l_i[i];
#pragma unroll
        for (int off = 8; off >= 1; off >>= 1)
            l += __shfl_xor_sync(0xffffffffu, l, off);
        float inv = 1.0f / l;
        int r = r0 + ty + 16 * i;
        if (r < S_TOT) {
            int gr = orig_idx(r);   // rotate-back == write at original index
            float* op = O + ((size_t)gr * NH + head) * HD;
            float4 o0 = acc_o[i][0], o1 = acc_o[i][1];
            o0.x *= inv; o0.y *= inv; o0.z *= inv; o0.w *= inv;
            o1.x *= inv; o1.y *= inv; o1.z *= inv; o1.w *= inv;
            *(float4*)(op +      tx * 4) = o0;
            *(float4*)(op + 64 + tx * 4) = o1;
        }
    }
}

// ---------------- recall ratio kernels ----------------
// grid: (130, NH, 2)  z=0 -> local (stride 1), z=1 -> global (stride 8)
__global__ __launch_bounds__(256)
void ratio_kernel(const float* __restrict__ Q, const float* __restrict__ K,
                  float* __restrict__ ratio)
{
    const int warp = threadIdx.x >> 5;
    const int lane = threadIdx.x & 31;
    const int row  = blockIdx.x * 8 + warp;      // 0..1039
    const int head = blockIdx.y;
    const int type = blockIdx.z;
    const int stride = type ? 8 : 1;

    const int gq = PF + row * stride;            // rotated row -> original index
    float4 qv = *(const float4*)(Q + ((size_t)gq * NH + head) * HD + lane * 4);

    float m = -INFINITY, lt = 0.f, lw = 0.f;
    for (int j = 0; j < PF; j++) {
        int gk = PF + j * stride;
        float4 kv = *(const float4*)(K + ((size_t)gk * NH + head) * HD + lane * 4);
        float d = qv.x * kv.x + qv.y * kv.y + qv.z * kv.z + qv.w * kv.w;
#pragma unroll
        for (int off = 16; off >= 1; off >>= 1)
            d += __shfl_xor_sync(0xffffffffu, d, off);
        float s = d * SCALE;
        float m_new = fmaxf(m, s);
        float sc = __expf(m - m_new);
        float p  = __expf(s - m_new);
        lt = lt * sc + p;
        lw = lw * sc + ((abs(row - j) <= WIN) ? p : 0.f);
        m = m_new;
    }
    if (lane == 0)
        atomicAdd(&ratio[type * NH + head], (lw / lt) * (1.0f / (float)PF));
}

__global__ void zero_ratio(float* r) {
    if (threadIdx.x < 4) r[threadIdx.x] = 0.f;
}

// ---------------- launch ----------------
extern "C" void kernel_launch(void* const* d_in, const int* in_sizes, int n_in,
                              void* d_out, int out_size)
{
    const float* Q = (const float*)d_in[0];
    const float* K = (const float*)d_in[1];
    const float* V = (const float*)d_in[2];
    float* O     = (float*)d_out;
    float* ratio = O + (size_t)S_TOT * NH * HD;   // [ratio_local(2) | ratio_global(2)]

    cudaFuncSetAttribute(attn_kernel, cudaFuncAttributeMaxDynamicSharedMemorySize, SMEM_BYTES);

    zero_ratio<<<1, 32>>>(ratio);
    dim3 rg(130, NH, 2);
    ratio_kernel<<<rg, 256>>>(Q, K, ratio);
    dim3 ag(NBLK, NH);
    attn_kernel<<<ag, 256, SMEM_BYTES>>>(Q, K, V, O);
}

// round 5
// speedup vs baseline: 3.1398x; 3.1398x over previous
#include <cuda_runtime.h>
#include <cuda_bf16.h>
#include <math.h>

typedef unsigned int u32;

// ---------------- problem constants ----------------
#define S_TOT 9616
#define RAZOR 8320
#define PF    1040
#define ROT   8576
#define NH    2
#define HD    128
#define PRE   2048
#define WIN   301
#define SCALE 0.08838834764831845f

// rotated bf16 split buffers [h][s][d]
__device__ __nv_bfloat16 g_Qh[(size_t)NH*S_TOT*HD];
__device__ __nv_bfloat16 g_Ql[(size_t)NH*S_TOT*HD];
__device__ __nv_bfloat16 g_Kh[(size_t)NH*S_TOT*HD];
__device__ __nv_bfloat16 g_Kl[(size_t)NH*S_TOT*HD];
__device__ __nv_bfloat16 g_Vh[(size_t)NH*S_TOT*HD];
__device__ __nv_bfloat16 g_Vl[(size_t)NH*S_TOT*HD];

__device__ __forceinline__ int orig_idx(int r) { return r < ROT ? r + PF : r - ROT; }

__device__ __forceinline__ u32 smem_u32(const void* p) {
    u32 a;
    asm("{ .reg .u64 t; cvta.to.shared.u64 t, %1; cvt.u32.u64 %0, t; }" : "=r"(a) : "l"(p));
    return a;
}
__device__ __forceinline__ void ldsm4(u32* r, u32 a) {
    asm volatile("ldmatrix.sync.aligned.m8n8.x4.shared.b16 {%0,%1,%2,%3}, [%4];"
                 : "=r"(r[0]), "=r"(r[1]), "=r"(r[2]), "=r"(r[3]) : "r"(a));
}
__device__ __forceinline__ void ldsm4t(u32* r, u32 a) {
    asm volatile("ldmatrix.sync.aligned.m8n8.x4.trans.shared.b16 {%0,%1,%2,%3}, [%4];"
                 : "=r"(r[0]), "=r"(r[1]), "=r"(r[2]), "=r"(r[3]) : "r"(a));
}
__device__ __forceinline__ void mma(float* d, const u32* a, u32 b0, u32 b1) {
    asm volatile("mma.sync.aligned.m16n8k16.row.col.f32.bf16.bf16.f32 "
                 "{%0,%1,%2,%3},{%4,%5,%6,%7},{%8,%9},{%0,%1,%2,%3};"
                 : "+f"(d[0]), "+f"(d[1]), "+f"(d[2]), "+f"(d[3])
                 : "r"(a[0]), "r"(a[1]), "r"(a[2]), "r"(a[3]), "r"(b0), "r"(b1));
}
__device__ __forceinline__ u32 pack2(float a, float b) {
    __nv_bfloat162 t = __floats2bfloat162_rn(a, b);
    return *(u32*)&t;
}
__device__ __forceinline__ u32 pack2lo(float a, float b, u32 hipk) {
    __nv_bfloat162 h = *(__nv_bfloat162*)&hipk;
    return pack2(a - __bfloat162float(h.x), b - __bfloat162float(h.y));
}

// ---------------- smem layout ----------------
#define RSTR 272                      // padded row stride bytes (128 bf16 + 16B pad)
#define SQH  0
#define SQL  (SQH + 128*RSTR)
#define SKH  (SQL + 128*RSTR)
#define SKL  (SKH + 64*RSTR)
#define SVH  (SKL + 64*RSTR)
#define SVL  (SVH + 64*RSTR)
#define SMEM_TOTAL (SVL + 64*RSTR)    // 139264 B

// ---------------- prep: rotate + bf16 split ----------------
__global__ __launch_bounds__(256) void prep_qkv(const float* __restrict__ Q,
                                                const float* __restrict__ K,
                                                const float* __restrict__ V) {
    int h = blockIdx.y;
    int s = blockIdx.x * 8 + (threadIdx.x >> 5);
    if (s >= S_TOT) return;
    int lane = threadIdx.x & 31;
    int gq = orig_idx(s);
    size_t si = ((size_t)gq * NH + h) * HD + lane * 4;
    size_t o  = ((size_t)h * S_TOT + s) * HD + lane * 4;
    float4 qv = *(const float4*)(Q + si);
    float4 kv = *(const float4*)(K + si);
    float4 vv = *(const float4*)(V + si);
    u32 qh0 = pack2(qv.x, qv.y), qh1 = pack2(qv.z, qv.w);
    u32 kh0 = pack2(kv.x, kv.y), kh1 = pack2(kv.z, kv.w);
    u32 vh0 = pack2(vv.x, vv.y), vh1 = pack2(vv.z, vv.w);
    *(uint2*)(g_Qh + o) = make_uint2(qh0, qh1);
    *(uint2*)(g_Ql + o) = make_uint2(pack2lo(qv.x, qv.y, qh0), pack2lo(qv.z, qv.w, qh1));
    *(uint2*)(g_Kh + o) = make_uint2(kh0, kh1);
    *(uint2*)(g_Kl + o) = make_uint2(pack2lo(kv.x, kv.y, kh0), pack2lo(kv.z, kv.w, kh1));
    *(uint2*)(g_Vh + o) = make_uint2(vh0, vh1);
    *(uint2*)(g_Vl + o) = make_uint2(pack2lo(vv.x, vv.y, vh0), pack2lo(vv.z, vv.w, vh1));
}

// ---------------- main attention: mma.sync bf16 3-split ----------------
__global__ __launch_bounds__(256, 1)
void attn_kernel(float* __restrict__ O)
{
    extern __shared__ char sm[];
    const u32 sb  = smem_u32(sm);
    const int tid = threadIdx.x, w = tid >> 5, lane = tid & 31;
    const int g = lane >> 2, tg = lane & 3;

    // schedule: tail tiles (151 iters) first, shortest razor tiles last
    const int head = blockIdx.x & 1;
    const int q    = blockIdx.x >> 1;          // 0..75
    const int tile = (q < 11) ? 65 + q : q - 11;
    const int r0   = tile * 128;
    const bool rowRazor = (tile < 65);

    const __nv_bfloat16* qh = g_Qh + (size_t)head * S_TOT * HD;
    const __nv_bfloat16* ql = g_Ql + (size_t)head * S_TOT * HD;
    const __nv_bfloat16* kh = g_Kh + (size_t)head * S_TOT * HD;
    const __nv_bfloat16* kl = g_Kl + (size_t)head * S_TOT * HD;
    const __nv_bfloat16* vh = g_Vh + (size_t)head * S_TOT * HD;
    const __nv_bfloat16* vl = g_Vl + (size_t)head * S_TOT * HD;

    // ---- load Q tile (once) ----
#pragma unroll
    for (int it = 0; it < 8; it++) {
        int idx = tid + it * 256;
        int row = idx >> 4, ch = idx & 15;
        size_t src = (size_t)min(r0 + row, S_TOT - 1) * HD + ch * 8;
        int dst = row * RSTR + ch * 16;
        *(uint4*)(sm + SQH + dst) = *(const uint4*)(qh + src);
        *(uint4*)(sm + SQL + dst) = *(const uint4*)(ql + src);
    }

    // ldmatrix base addresses
    const u32 aAddr = sb + SQH + (w * 16 + (lane & 15)) * RSTR + (lane >> 4) * 16;
    const u32 bAddrK = sb + SKH + ((lane & 7) + ((lane >> 4) & 1) * 8) * RSTR
                     + ((lane >> 3) & 1) * 16;
    const u32 bAddrV = sb + SVH + ((lane & 7) + ((lane >> 3) & 1) * 8) * RSTR
                     + ((lane >> 4) & 1) * 16;

    float o[16][4];
#pragma unroll
    for (int i = 0; i < 16; i++)
#pragma unroll
        for (int j = 0; j < 4; j++) o[i][j] = 0.f;
    float laccA = 0.f, laccB = 0.f;
    const int rA = r0 + w * 16 + g, rB = rA + 8;

    int lo0, hi0, lo1, hi1;
    if (rowRazor) { lo0 = max(0, 2*tile - 32); hi0 = min(129, 2*tile + 33); lo1 = 130; hi1 = 150; }
    else          { lo0 = 0; hi0 = 150; lo1 = 0; hi1 = -1; }

    for (int seg = 0; seg < 2; seg++)
    for (int blk = (seg ? lo1 : lo0); blk <= (seg ? hi1 : hi0); blk++) {
        const int c0 = blk * 64;
        // maskMode: 0 none, 1 band edge, 2 seq tail
        int maskMode = 0;
        if (blk < 130) { if (rowRazor && (blk < 2*tile - 30 || blk > 2*tile + 31)) maskMode = 1; }
        else if (blk == 150) maskMode = 2;

        __syncthreads();   // previous iter's mma reads done before overwrite
        // ---- load K + V block (identical [pos][d] layout) ----
#pragma unroll
        for (int it = 0; it < 4; it++) {
            int idx = tid + it * 256;
            int row = idx >> 4, ch = idx & 15;
            size_t src = (size_t)min(c0 + row, S_TOT - 1) * HD + ch * 8;
            int dst = row * RSTR + ch * 16;
            *(uint4*)(sm + SKH + dst) = *(const uint4*)(kh + src);
            *(uint4*)(sm + SKL + dst) = *(const uint4*)(kl + src);
            *(uint4*)(sm + SVH + dst) = *(const uint4*)(vh + src);
            *(uint4*)(sm + SVL + dst) = *(const uint4*)(vl + src);
        }
        __syncthreads();

        // ---- QK: S = QhKh + QhKl + QlKh ----
        float s[8][4];
#pragma unroll
        for (int i = 0; i < 8; i++)
#pragma unroll
            for (int j = 0; j < 4; j++) s[i][j] = 0.f;

#pragma unroll
        for (int kc = 0; kc < 8; kc++) {
            u32 Ah[4], Al[4];
            ldsm4(Ah, aAddr + kc * 32);
            ldsm4(Al, aAddr + (SQL - SQH) + kc * 32);
#pragma unroll
            for (int nb2 = 0; nb2 < 4; nb2++) {
                u32 Bh[4], Bl[4];
                u32 ba = bAddrK + nb2 * (16 * RSTR) + kc * 32;
                ldsm4(Bh, ba);
                ldsm4(Bl, ba + (SKL - SKH));
                mma(s[2*nb2],   Ah, Bh[0], Bh[1]);
                mma(s[2*nb2],   Ah, Bl[0], Bl[1]);
                mma(s[2*nb2],   Al, Bh[0], Bh[1]);
                mma(s[2*nb2+1], Ah, Bh[2], Bh[3]);
                mma(s[2*nb2+1], Ah, Bl[2], Bl[3]);
                mma(s[2*nb2+1], Al, Bh[2], Bh[3]);
            }
        }

        // ---- epilogue: mask + exp + split-pack ----
        u32 ph[8][2], pl[8][2];
#pragma unroll
        for (int nb = 0; nb < 8; nb++) {
            int c = c0 + nb * 8 + 2 * tg;
            float p00 = __expf(s[nb][0] * SCALE);
            float p01 = __expf(s[nb][1] * SCALE);
            float p10 = __expf(s[nb][2] * SCALE);
            float p11 = __expf(s[nb][3] * SCALE);
            if (maskMode == 1) {
                if ((unsigned)(c     - (rA - PRE)) > 2u*PRE) p00 = 0.f;
                if ((unsigned)(c + 1 - (rA - PRE)) > 2u*PRE) p01 = 0.f;
                if ((unsigned)(c     - (rB - PRE)) > 2u*PRE) p10 = 0.f;
                if ((unsigned)(c + 1 - (rB - PRE)) > 2u*PRE) p11 = 0.f;
            } else if (maskMode == 2) {
                if (c     >= S_TOT) { p00 = 0.f; p10 = 0.f; }
                if (c + 1 >= S_TOT) { p01 = 0.f; p11 = 0.f; }
            }
            laccA += p00 + p01;
            laccB += p10 + p11;
            ph[nb][0] = pack2(p00, p01); pl[nb][0] = pack2lo(p00, p01, ph[nb][0]);
            ph[nb][1] = pack2(p10, p11); pl[nb][1] = pack2lo(p10, p11, ph[nb][1]);
        }

        // ---- PV: O += PhVh + PhVl + PlVh ----
#pragma unroll
        for (int kc = 0; kc < 4; kc++) {
            u32 Ah[4] = { ph[2*kc][0], ph[2*kc][1], ph[2*kc+1][0], ph[2*kc+1][1] };
            u32 Al[4] = { pl[2*kc][0], pl[2*kc][1], pl[2*kc+1][0], pl[2*kc+1][1] };
#pragma unroll
            for (int nb2 = 0; nb2 < 8; nb2++) {
                u32 Bh[4], Bl[4];
                u32 ba = bAddrV + kc * (16 * RSTR) + nb2 * 32;
                ldsm4t(Bh, ba);
                ldsm4t(Bl, ba + (SVL - SVH));
                mma(o[2*nb2],   Ah, Bh[0], Bh[1]);
                mma(o[2*nb2],   Ah, Bl[0], Bl[1]);
                mma(o[2*nb2],   Al, Bh[0], Bh[1]);
                mma(o[2*nb2+1], Ah, Bh[2], Bh[3]);
                mma(o[2*nb2+1], Ah, Bl[2], Bl[3]);
                mma(o[2*nb2+1], Al, Bh[2], Bh[3]);
            }
        }
    }

    // ---- finalize: reduce l across quad lanes, normalize, store ----
    laccA += __shfl_xor_sync(0xffffffffu, laccA, 1);
    laccA += __shfl_xor_sync(0xffffffffu, laccA, 2);
    laccB += __shfl_xor_sync(0xffffffffu, laccB, 1);
    laccB += __shfl_xor_sync(0xffffffffu, laccB, 2);
    float invA = 1.f / laccA, invB = 1.f / laccB;

    if (rA < S_TOT) {
        float* base = O + ((size_t)orig_idx(rA) * NH + head) * HD;
#pragma unroll
        for (int nb = 0; nb < 16; nb++)
            *(float2*)(base + nb * 8 + 2 * tg) = make_float2(o[nb][0] * invA, o[nb][1] * invA);
    }
    if (rB < S_TOT) {
        float* base = O + ((size_t)orig_idx(rB) * NH + head) * HD;
#pragma unroll
        for (int nb = 0; nb < 16; nb++)
            *(float2*)(base + nb * 8 + 2 * tg) = make_float2(o[nb][2] * invB, o[nb][3] * invB);
    }
}

// ---------------- recall ratio kernels (known good) ----------------
__global__ __launch_bounds__(256)
void ratio_kernel(const float* __restrict__ Q, const float* __restrict__ K,
                  float* __restrict__ ratio)
{
    const int warp = threadIdx.x >> 5;
    const int lane = threadIdx.x & 31;
    const int row  = blockIdx.x * 8 + warp;
    const int head = blockIdx.y;
    const int type = blockIdx.z;
    const int stride = type ? 8 : 1;

    const int gq = PF + row * stride;
    float4 qv = *(const float4*)(Q + ((size_t)gq * NH + head) * HD + lane * 4);

    float m = -INFINITY, lt = 0.f, lw = 0.f;
    for (int j = 0; j < PF; j++) {
        int gk = PF + j * stride;
        float4 kv = *(const float4*)(K + ((size_t)gk * NH + head) * HD + lane * 4);
        float d = qv.x * kv.x + qv.y * kv.y + qv.z * kv.z + qv.w * kv.w;
#pragma unroll
        for (int off = 16; off >= 1; off >>= 1)
            d += __shfl_xor_sync(0xffffffffu, d, off);
        float s = d * SCALE;
        float m_new = fmaxf(m, s);
        float sc = __expf(m - m_new);
        float p  = __expf(s - m_new);
        lt = lt * sc + p;
        lw = lw * sc + ((abs(row - j) <= WIN) ? p : 0.f);
        m = m_new;
    }
    if (lane == 0)
        atomicAdd(&ratio[type * NH + head], (lw / lt) * (1.0f / (float)PF));
}

__global__ void zero_ratio(float* r) {
    if (threadIdx.x < 4) r[threadIdx.x] = 0.f;
}

// ---------------- launch ----------------
extern "C" void kernel_launch(void* const* d_in, const int* in_sizes, int n_in,
                              void* d_out, int out_size)
{
    const float* Q = (const float*)d_in[0];
    const float* K = (const float*)d_in[1];
    const float* V = (const float*)d_in[2];
    float* O     = (float*)d_out;
    float* ratio = O + (size_t)S_TOT * NH * HD;

    cudaFuncSetAttribute(attn_kernel, cudaFuncAttributeMaxDynamicSharedMemorySize, SMEM_TOTAL);

    zero_ratio<<<1, 32>>>(ratio);
    prep_qkv<<<dim3(1202, NH), 256>>>(Q, K, V);
    ratio_kernel<<<dim3(130, NH, 2), 256>>>(Q, K, ratio);
    attn_kernel<<<152, 256, SMEM_TOTAL>>>(O);
}

// round 6
// speedup vs baseline: 5.4188x; 1.7259x over previous
#include <cuda_runtime.h>
#include <cuda_bf16.h>
#include <math.h>

typedef unsigned int u32;

// ---------------- problem constants ----------------
#define S_TOT 9616
#define RAZOR 8320
#define PF    1040
#define ROT   8576
#define NH    2
#define HD    128
#define PRE   2048
#define WIN   301
#define SCALE 0.08838834764831845f

// rotated bf16 split buffers [h][s][d]
__device__ __nv_bfloat16 g_Qh[(size_t)NH*S_TOT*HD];
__device__ __nv_bfloat16 g_Ql[(size_t)NH*S_TOT*HD];
__device__ __nv_bfloat16 g_Kh[(size_t)NH*S_TOT*HD];
__device__ __nv_bfloat16 g_Kl[(size_t)NH*S_TOT*HD];
__device__ __nv_bfloat16 g_Vh[(size_t)NH*S_TOT*HD];
__device__ __nv_bfloat16 g_Vl[(size_t)NH*S_TOT*HD];

// tail-tile partial scratch: 11 tiles x 2 heads x 8 chunks
#define NCHUNK 8
__device__ float g_scrO[(size_t)11*2*NCHUNK*128*128];
__device__ float g_scrL[(size_t)11*2*NCHUNK*128];

__device__ __forceinline__ int orig_idx(int r) { return r < ROT ? r + PF : r - ROT; }

__device__ __forceinline__ u32 smem_u32(const void* p) {
    u32 a;
    asm("{ .reg .u64 t; cvta.to.shared.u64 t, %1; cvt.u32.u64 %0, t; }" : "=r"(a) : "l"(p));
    return a;
}
__device__ __forceinline__ void ldsm4(u32* r, u32 a) {
    asm volatile("ldmatrix.sync.aligned.m8n8.x4.shared.b16 {%0,%1,%2,%3}, [%4];"
                 : "=r"(r[0]), "=r"(r[1]), "=r"(r[2]), "=r"(r[3]) : "r"(a));
}
__device__ __forceinline__ void ldsm4t(u32* r, u32 a) {
    asm volatile("ldmatrix.sync.aligned.m8n8.x4.trans.shared.b16 {%0,%1,%2,%3}, [%4];"
                 : "=r"(r[0]), "=r"(r[1]), "=r"(r[2]), "=r"(r[3]) : "r"(a));
}
__device__ __forceinline__ void mma(float* d, const u32* a, u32 b0, u32 b1) {
    asm volatile("mma.sync.aligned.m16n8k16.row.col.f32.bf16.bf16.f32 "
                 "{%0,%1,%2,%3},{%4,%5,%6,%7},{%8,%9},{%0,%1,%2,%3};"
                 : "+f"(d[0]), "+f"(d[1]), "+f"(d[2]), "+f"(d[3])
                 : "r"(a[0]), "r"(a[1]), "r"(a[2]), "r"(a[3]), "r"(b0), "r"(b1));
}
__device__ __forceinline__ u32 pack2(float a, float b) {
    __nv_bfloat162 t = __floats2bfloat162_rn(a, b);
    return *(u32*)&t;
}
__device__ __forceinline__ u32 pack2lo(float a, float b, u32 hipk) {
    __nv_bfloat162 h = *(__nv_bfloat162*)&hipk;
    return pack2(a - __bfloat162float(h.x), b - __bfloat162float(h.y));
}

#define CP_ASYNC16(d, s) asm volatile("cp.async.cg.shared.global [%0], [%1], 16;" :: "r"(d), "l"(s))
#define CP_COMMIT()      asm volatile("cp.async.commit_group;" ::: "memory")
#define CP_WAIT0()       asm volatile("cp.async.wait_group 0;" ::: "memory")

// ---------------- smem layout ----------------
#define RSTR 272                       // padded row stride bytes
#define QTILE (128*RSTR)               // 34816
#define KROWS (64*RSTR)                // 17408
#define KVBUF (4*KROWS)                // 69632: [KH|KL|VH|VL]
#define SKV0  (2*QTILE)                // 69632
#define SMEM_ATTN (SKV0 + 2*KVBUF)    // 208896
#define SMEM_RATIO (2*QTILE + 2*KROWS) // 104448

// ---------------- prep: rotate + bf16 split ----------------
__global__ __launch_bounds__(256) void prep_qkv(const float* __restrict__ Q,
                                                const float* __restrict__ K,
                                                const float* __restrict__ V) {
    int h = blockIdx.y;
    int s = blockIdx.x * 8 + (threadIdx.x >> 5);
    if (s >= S_TOT) return;
    int lane = threadIdx.x & 31;
    int gq = orig_idx(s);
    size_t si = ((size_t)gq * NH + h) * HD + lane * 4;
    size_t o  = ((size_t)h * S_TOT + s) * HD + lane * 4;
    float4 qv = *(const float4*)(Q + si);
    float4 kv = *(const float4*)(K + si);
    float4 vv = *(const float4*)(V + si);
    u32 qh0 = pack2(qv.x, qv.y), qh1 = pack2(qv.z, qv.w);
    u32 kh0 = pack2(kv.x, kv.y), kh1 = pack2(kv.z, kv.w);
    u32 vh0 = pack2(vv.x, vv.y), vh1 = pack2(vv.z, vv.w);
    *(uint2*)(g_Qh + o) = make_uint2(qh0, qh1);
    *(uint2*)(g_Ql + o) = make_uint2(pack2lo(qv.x, qv.y, qh0), pack2lo(qv.z, qv.w, qh1));
    *(uint2*)(g_Kh + o) = make_uint2(kh0, kh1);
    *(uint2*)(g_Kl + o) = make_uint2(pack2lo(kv.x, kv.y, kh0), pack2lo(kv.z, kv.w, kh1));
    *(uint2*)(g_Vh + o) = make_uint2(vh0, vh1);
    *(uint2*)(g_Vl + o) = make_uint2(pack2lo(vv.x, vv.y, vh0), pack2lo(vv.z, vv.w, vh1));
}

// ---------------- async KV block load ----------------
__device__ __forceinline__ void kv_load(u32 kvb, int c0, int tid,
    const __nv_bfloat16* kh, const __nv_bfloat16* kl,
    const __nv_bfloat16* vh, const __nv_bfloat16* vl)
{
#pragma unroll
    for (int it = 0; it < 4; it++) {
        int idx = tid + it * 256;
        int row = idx >> 4, ch = idx & 15;
        size_t src = (size_t)min(c0 + row, S_TOT - 1) * HD + ch * 8;
        u32 dst = kvb + row * RSTR + ch * 16;
        CP_ASYNC16(dst,             kh + src);
        CP_ASYNC16(dst + KROWS,     kl + src);
        CP_ASYNC16(dst + 2*KROWS,   vh + src);
        CP_ASYNC16(dst + 3*KROWS,   vl + src);
    }
}

// ---------------- main attention: mma.sync bf16 3-split, pipelined ----------------
__global__ __launch_bounds__(256, 1)
void attn_kernel(float* __restrict__ O)
{
    extern __shared__ char sm[];
    const u32 sb  = smem_u32(sm);
    const int tid = threadIdx.x, w = tid >> 5, lane = tid & 31;
    const int g = lane >> 2, tg = lane & 3;

    // grid: 130 razor CTAs first (longest), then 176 tail chunks (19 iters each)
    int tile, head, chunk = -1, eidx = 0;
    int lo0, hi0, lo1, hi1;
    if (blockIdx.x < 130) {
        tile = blockIdx.x >> 1; head = blockIdx.x & 1;
        lo0 = max(0, 2*tile - 32); hi0 = min(129, 2*tile + 33);
        lo1 = 130; hi1 = 150;
    } else {
        int e = blockIdx.x - 130;            // 0..175
        int tileIdx = e >> 4; head = (e >> 3) & 1; chunk = e & 7;
        tile = 65 + tileIdx;
        eidx = e;
        lo0 = chunk * 19; hi0 = min(150, chunk * 19 + 18);
        lo1 = 0; hi1 = -1;
    }
    const int r0 = tile * 128;
    const bool rowRazor = (tile < 65);
    const int n0 = hi0 - lo0 + 1;
    const int nb_total = n0 + (hi1 >= lo1 ? hi1 - lo1 + 1 : 0);

    const __nv_bfloat16* qh = g_Qh + (size_t)head * S_TOT * HD;
    const __nv_bfloat16* ql = g_Ql + (size_t)head * S_TOT * HD;
    const __nv_bfloat16* kh = g_Kh + (size_t)head * S_TOT * HD;
    const __nv_bfloat16* kl = g_Kl + (size_t)head * S_TOT * HD;
    const __nv_bfloat16* vh = g_Vh + (size_t)head * S_TOT * HD;
    const __nv_bfloat16* vl = g_Vl + (size_t)head * S_TOT * HD;

    // prologue: issue first KV block async, then load Q tile
    kv_load(sb + SKV0, (lo0) * 64, tid, kh, kl, vh, vl);
    CP_COMMIT();

#pragma unroll
    for (int it = 0; it < 8; it++) {
        int idx = tid + it * 256;
        int row = idx >> 4, ch = idx & 15;
        size_t src = (size_t)min(r0 + row, S_TOT - 1) * HD + ch * 8;
        int dst = row * RSTR + ch * 16;
        *(uint4*)(sm + dst)          = *(const uint4*)(qh + src);
        *(uint4*)(sm + QTILE + dst)  = *(const uint4*)(ql + src);
    }

    const u32 aAddr = sb + (w * 16 + (lane & 15)) * RSTR + (lane >> 4) * 16;
    const u32 offBK = ((lane & 7) + ((lane >> 4) & 1) * 8) * RSTR + ((lane >> 3) & 1) * 16;
    const u32 offBV = 2*KROWS + ((lane & 7) + ((lane >> 3) & 1) * 8) * RSTR + ((lane >> 4) & 1) * 16;

    float o[16][4];
#pragma unroll
    for (int i = 0; i < 16; i++)
#pragma unroll
        for (int j = 0; j < 4; j++) o[i][j] = 0.f;
    float laccA = 0.f, laccB = 0.f;
    const int rA = r0 + w * 16 + g, rB = rA + 8;

    for (int i = 0; i < nb_total; i++) {
        const int blk = (i < n0) ? lo0 + i : lo1 + (i - n0);
        const int c0 = blk * 64;
        int maskMode = 0;
        if (blk < 130) { if (rowRazor && (blk < 2*tile - 30 || blk > 2*tile + 31)) maskMode = 1; }
        else if (blk == 150) maskMode = 2;

        CP_WAIT0();
        __syncthreads();
        if (i + 1 < nb_total) {
            const int nblk = (i + 1 < n0) ? lo0 + i + 1 : lo1 + (i + 1 - n0);
            kv_load(sb + SKV0 + ((i + 1) & 1) * KVBUF, nblk * 64, tid, kh, kl, vh, vl);
            CP_COMMIT();
        }
        const u32 kvb = sb + SKV0 + (i & 1) * KVBUF;

        // ---- QK: S = QhKh + QhKl + QlKh ----
        float s[8][4];
#pragma unroll
        for (int x = 0; x < 8; x++)
#pragma unroll
            for (int j = 0; j < 4; j++) s[x][j] = 0.f;

#pragma unroll
        for (int kc = 0; kc < 8; kc++) {
            u32 Ah[4], Al[4];
            ldsm4(Ah, aAddr + kc * 32);
            ldsm4(Al, aAddr + QTILE + kc * 32);
#pragma unroll
            for (int nb2 = 0; nb2 < 4; nb2++) {
                u32 Bh[4], Bl[4];
                u32 ba = kvb + offBK + nb2 * (16 * RSTR) + kc * 32;
                ldsm4(Bh, ba);
                ldsm4(Bl, ba + KROWS);
                mma(s[2*nb2],   Ah, Bh[0], Bh[1]);
                mma(s[2*nb2],   Ah, Bl[0], Bl[1]);
                mma(s[2*nb2],   Al, Bh[0], Bh[1]);
                mma(s[2*nb2+1], Ah, Bh[2], Bh[3]);
                mma(s[2*nb2+1], Ah, Bl[2], Bl[3]);
                mma(s[2*nb2+1], Al, Bh[2], Bh[3]);
            }
        }

        // ---- epilogue: mask + exp + split-pack ----
        u32 ph[8][2], pl[8][2];
#pragma unroll
        for (int nb = 0; nb < 8; nb++) {
            int c = c0 + nb * 8 + 2 * tg;
            float p00 = __expf(s[nb][0] * SCALE);
            float p01 = __expf(s[nb][1] * SCALE);
            float p10 = __expf(s[nb][2] * SCALE);
            float p11 = __expf(s[nb][3] * SCALE);
            if (maskMode == 1) {
                if ((unsigned)(c     - (rA - PRE)) > 2u*PRE) p00 = 0.f;
                if ((unsigned)(c + 1 - (rA - PRE)) > 2u*PRE) p01 = 0.f;
                if ((unsigned)(c     - (rB - PRE)) > 2u*PRE) p10 = 0.f;
                if ((unsigned)(c + 1 - (rB - PRE)) > 2u*PRE) p11 = 0.f;
            } else if (maskMode == 2) {
                if (c     >= S_TOT) { p00 = 0.f; p10 = 0.f; }
                if (c + 1 >= S_TOT) { p01 = 0.f; p11 = 0.f; }
            }
            laccA += p00 + p01;
            laccB += p10 + p11;
            ph[nb][0] = pack2(p00, p01); pl[nb][0] = pack2lo(p00, p01, ph[nb][0]);
            ph[nb][1] = pack2(p10, p11); pl[nb][1] = pack2lo(p10, p11, ph[nb][1]);
        }

        // ---- PV: O += PhVh + PhVl + PlVh ----
#pragma unroll
        for (int kc = 0; kc < 4; kc++) {
            u32 Ah[4] = { ph[2*kc][0], ph[2*kc][1], ph[2*kc+1][0], ph[2*kc+1][1] };
            u32 Al[4] = { pl[2*kc][0], pl[2*kc][1], pl[2*kc+1][0], pl[2*kc+1][1] };
#pragma unroll
            for (int nb2 = 0; nb2 < 8; nb2++) {
                u32 Bh[4], Bl[4];
                u32 ba = kvb + offBV + kc * (16 * RSTR) + nb2 * 32;
                ldsm4t(Bh, ba);
                ldsm4t(Bl, ba + KROWS);
                mma(o[2*nb2],   Ah, Bh[0], Bh[1]);
                mma(o[2*nb2],   Ah, Bl[0], Bl[1]);
                mma(o[2*nb2],   Al, Bh[0], Bh[1]);
                mma(o[2*nb2+1], Ah, Bh[2], Bh[3]);
                mma(o[2*nb2+1], Ah, Bl[2], Bl[3]);
                mma(o[2*nb2+1], Al, Bh[2], Bh[3]);
            }
        }
    }

    // ---- finalize ----
    laccA += __shfl_xor_sync(0xffffffffu, laccA, 1);
    laccA += __shfl_xor_sync(0xffffffffu, laccA, 2);
    laccB += __shfl_xor_sync(0xffffffffu, laccB, 1);
    laccB += __shfl_xor_sync(0xffffffffu, laccB, 2);

    if (chunk < 0) {
        // razor tile: normalize + direct store
        float invA = 1.f / laccA, invB = 1.f / laccB;
        if (rA < S_TOT) {
            float* base = O + ((size_t)orig_idx(rA) * NH + head) * HD;
#pragma unroll
            for (int nb = 0; nb < 16; nb++)
                *(float2*)(base + nb * 8 + 2 * tg) = make_float2(o[nb][0] * invA, o[nb][1] * invA);
        }
        if (rB < S_TOT) {
            float* base = O + ((size_t)orig_idx(rB) * NH + head) * HD;
#pragma unroll
            for (int nb = 0; nb < 16; nb++)
                *(float2*)(base + nb * 8 + 2 * tg) = make_float2(o[nb][2] * invB, o[nb][3] * invB);
        }
    } else {
        // tail chunk: write unnormalized partials to scratch
        float* so = g_scrO + (size_t)eidx * 16384;
        int rlA = w * 16 + g, rlB = rlA + 8;
#pragma unroll
        for (int nb = 0; nb < 16; nb++) {
            *(float2*)(so + rlA * 128 + nb * 8 + 2 * tg) = make_float2(o[nb][0], o[nb][1]);
            *(float2*)(so + rlB * 128 + nb * 8 + 2 * tg) = make_float2(o[nb][2], o[nb][3]);
        }
        if (tg == 0) {
            g_scrL[eidx * 128 + rlA] = laccA;
            g_scrL[eidx * 128 + rlB] = laccB;
        }
    }
}

// ---------------- combine tail partials ----------------
__global__ __launch_bounds__(256) void combine_kernel(float* __restrict__ O) {
    int b = blockIdx.x;                    // 0..21
    int tileIdx = b >> 1, head = b & 1;
    int tile = 65 + tileIdx, r0 = tile * 128;
    int ebase = tileIdx * 16 + head * 8;
    int tid = threadIdx.x;

    __shared__ float ls[128];
    if (tid < 128) {
        float sum = 0.f;
#pragma unroll
        for (int c = 0; c < NCHUNK; c++) sum += g_scrL[(ebase + c) * 128 + tid];
        ls[tid] = 1.f / sum;
    }
    __syncthreads();

    for (int k = tid; k < 16384; k += 256) {
        int row = k >> 7, col = k & 127;
        if (r0 + row >= S_TOT) continue;
        float sum = 0.f;
#pragma unroll
        for (int c = 0; c < NCHUNK; c++) sum += g_scrO[(size_t)(ebase + c) * 16384 + k];
        int gr = orig_idx(r0 + row);
        O[((size_t)gr * NH + head) * HD + col] = sum * ls[row];
    }
}

// ---------------- recall ratios via mma ----------------
__global__ __launch_bounds__(256) void ratio2_kernel(float* __restrict__ ratio) {
    extern __shared__ char sm[];
    const u32 sb = smem_u32(sm);
    const int tid = threadIdx.x, w = tid >> 5, lane = tid & 31;
    const int g = lane >> 2, tg = lane & 3;
    const int rb = blockIdx.x, head = blockIdx.y, type = blockIdx.z;
    const int r0 = rb * 128;
    const int stride = type ? 8 : 1;

    const __nv_bfloat16* qh = g_Qh + (size_t)head * S_TOT * HD;
    const __nv_bfloat16* ql = g_Ql + (size_t)head * S_TOT * HD;
    const __nv_bfloat16* kh = g_Kh + (size_t)head * S_TOT * HD;
    const __nv_bfloat16* kl = g_Kl + (size_t)head * S_TOT * HD;

#pragma unroll
    for (int it = 0; it < 8; it++) {
        int idx = tid + it * 256;
        int row = idx >> 4, ch = idx & 15;
        size_t src = (size_t)(min(r0 + row, PF - 1) * stride) * HD + ch * 8;
        int dst = row * RSTR + ch * 16;
        *(uint4*)(sm + dst)         = *(const uint4*)(qh + src);
        *(uint4*)(sm + QTILE + dst) = *(const uint4*)(ql + src);
    }

    const u32 aAddr = sb + (w * 16 + (lane & 15)) * RSTR + (lane >> 4) * 16;
    const u32 bAddr = sb + 2*QTILE + ((lane & 7) + ((lane >> 4) & 1) * 8) * RSTR
                    + ((lane >> 3) & 1) * 16;

    float totA = 0.f, winA = 0.f, totB = 0.f, winB = 0.f;
    const int rA = r0 + w * 16 + g, rB = rA + 8;

    for (int blk = 0; blk < 17; blk++) {
        const int c0 = blk * 64;
        __syncthreads();
#pragma unroll
        for (int it = 0; it < 4; it++) {
            int idx = tid + it * 256;
            int row = idx >> 4, ch = idx & 15;
            size_t src = (size_t)(min(c0 + row, PF - 1) * stride) * HD + ch * 8;
            int dst = 2*QTILE + row * RSTR + ch * 16;
            *(uint4*)(sm + dst)         = *(const uint4*)(kh + src);
            *(uint4*)(sm + dst + KROWS) = *(const uint4*)(kl + src);
        }
        __syncthreads();

        float s[8][4];
#pragma unroll
        for (int x = 0; x < 8; x++)
#pragma unroll
            for (int j = 0; j < 4; j++) s[x][j] = 0.f;
#pragma unroll
        for (int kc = 0; kc < 8; kc++) {
            u32 Ah[4], Al[4];
            ldsm4(Ah, aAddr + kc * 32);
            ldsm4(Al, aAddr + QTILE + kc * 32);
#pragma unroll
            for (int nb2 = 0; nb2 < 4; nb2++) {
                u32 Bh[4], Bl[4];
                u32 ba = bAddr + nb2 * (16 * RSTR) + kc * 32;
                ldsm4(Bh, ba);
                ldsm4(Bl, ba + KROWS);
                mma(s[2*nb2],   Ah, Bh[0], Bh[1]);
                mma(s[2*nb2],   Ah, Bl[0], Bl[1]);
                mma(s[2*nb2],   Al, Bh[0], Bh[1]);
                mma(s[2*nb2+1], Ah, Bh[2], Bh[3]);
                mma(s[2*nb2+1], Ah, Bl[2], Bl[3]);
                mma(s[2*nb2+1], Al, Bh[2], Bh[3]);
            }
        }
#pragma unroll
        for (int nb = 0; nb < 8; nb++) {
            int c = c0 + nb * 8 + 2 * tg;
#pragma unroll
            for (int v = 0; v < 4; v++) {
                int cc = c + (v & 1);
                int rr = (v < 2) ? rA : rB;
                float p = (cc < PF) ? __expf(s[nb][v] * SCALE) : 0.f;
                if (v < 2) { totA += p; if (abs(rr - cc) <= WIN) winA += p; }
                else       { totB += p; if (abs(rr - cc) <= WIN) winB += p; }
            }
        }
    }

    totA += __shfl_xor_sync(0xffffffffu, totA, 1);
    totA += __shfl_xor_sync(0xffffffffu, totA, 2);
    winA += __shfl_xor_sync(0xffffffffu, winA, 1);
    winA += __shfl_xor_sync(0xffffffffu, winA, 2);
    totB += __shfl_xor_sync(0xffffffffu, totB, 1);
    totB += __shfl_xor_sync(0xffffffffu, totB, 2);
    winB += __shfl_xor_sync(0xffffffffu, winB, 1);
    winB += __shfl_xor_sync(0xffffffffu, winB, 2);

    float* red = (float*)sm;
    __syncthreads();
    if (tid == 0) red[0] = 0.f;
    __syncthreads();
    if (tg == 0) {
        float contrib = 0.f;
        if (rA < PF) contrib += winA / totA;
        if (rB < PF) contrib += winB / totB;
        if (contrib != 0.f) atomicAdd(red, contrib);
    }
    __syncthreads();
    if (tid == 0) atomicAdd(&ratio[type * NH + head], red[0] * (1.f / (float)PF));
}

__global__ void zero_ratio(float* r) {
    if (threadIdx.x < 4) r[threadIdx.x] = 0.f;
}

// ---------------- launch ----------------
extern "C" void kernel_launch(void* const* d_in, const int* in_sizes, int n_in,
                              void* d_out, int out_size)
{
    const float* Q = (const float*)d_in[0];
    const float* K = (const float*)d_in[1];
    const float* V = (const float*)d_in[2];
    float* O     = (float*)d_out;
    float* ratio = O + (size_t)S_TOT * NH * HD;

    cudaFuncSetAttribute(attn_kernel,   cudaFuncAttributeMaxDynamicSharedMemorySize, SMEM_ATTN);
    cudaFuncSetAttribute(ratio2_kernel, cudaFuncAttributeMaxDynamicSharedMemorySize, SMEM_RATIO);

    zero_ratio<<<1, 32>>>(ratio);
    prep_qkv<<<dim3(1202, NH), 256>>>(Q, K, V);
    ratio2_kernel<<<dim3(9, NH, 2), 256, SMEM_RATIO>>>(ratio);
    attn_kernel<<<306, 256, SMEM_ATTN>>>(O);
    combine_kernel<<<22, 256>>>(O);
}

// round 7
// speedup vs baseline: 6.4191x; 1.1846x over previous
#include <cuda_runtime.h>
#include <cuda_fp16.h>
#include <math.h>

typedef unsigned int u32;

// ---------------- problem constants ----------------
#define S_TOT 9616
#define RAZOR 8320
#define PF    1040
#define ROT   8576
#define NH    2
#define HD    128
#define PRE   2048
#define WIN   301
#define SCALE 0.08838834764831845f

// rotated fp16 split buffers [h][s][d]
__device__ __half g_Qh[(size_t)NH*S_TOT*HD];
__device__ __half g_Ql[(size_t)NH*S_TOT*HD];
__device__ __half g_Kh[(size_t)NH*S_TOT*HD];
__device__ __half g_Kl[(size_t)NH*S_TOT*HD];
__device__ __half g_Vh[(size_t)NH*S_TOT*HD];
__device__ __half g_Vl[(size_t)NH*S_TOT*HD];

// tail-tile partial scratch: 11 tiles x 2 heads x 8 chunks
#define NCHUNK 8
__device__ float g_scrO[(size_t)11*2*NCHUNK*128*128];
__device__ float g_scrL[(size_t)11*2*NCHUNK*128];

__device__ __forceinline__ int orig_idx(int r) { return r < ROT ? r + PF : r - ROT; }

__device__ __forceinline__ u32 smem_u32(const void* p) {
    u32 a;
    asm("{ .reg .u64 t; cvta.to.shared.u64 t, %1; cvt.u32.u64 %0, t; }" : "=r"(a) : "l"(p));
    return a;
}
__device__ __forceinline__ void ldsm4(u32* r, u32 a) {
    asm volatile("ldmatrix.sync.aligned.m8n8.x4.shared.b16 {%0,%1,%2,%3}, [%4];"
                 : "=r"(r[0]), "=r"(r[1]), "=r"(r[2]), "=r"(r[3]) : "r"(a));
}
__device__ __forceinline__ void ldsm4t(u32* r, u32 a) {
    asm volatile("ldmatrix.sync.aligned.m8n8.x4.trans.shared.b16 {%0,%1,%2,%3}, [%4];"
                 : "=r"(r[0]), "=r"(r[1]), "=r"(r[2]), "=r"(r[3]) : "r"(a));
}
__device__ __forceinline__ void mma(float* d, const u32* a, u32 b0, u32 b1) {
    asm volatile("mma.sync.aligned.m16n8k16.row.col.f32.f16.f16.f32 "
                 "{%0,%1,%2,%3},{%4,%5,%6,%7},{%8,%9},{%0,%1,%2,%3};"
                 : "+f"(d[0]), "+f"(d[1]), "+f"(d[2]), "+f"(d[3])
                 : "r"(a[0]), "r"(a[1]), "r"(a[2]), "r"(a[3]), "r"(b0), "r"(b1));
}
__device__ __forceinline__ u32 pack2(float a, float b) {
    __half2 t = __floats2half2_rn(a, b);
    return *(u32*)&t;
}
__device__ __forceinline__ u32 pack2lo(float a, float b, u32 hipk) {
    __half2 h = *(__half2*)&hipk;
    return pack2(a - __half2float(h.x), b - __half2float(h.y));
}

#define CP_ASYNC16(d, s) asm volatile("cp.async.cg.shared.global [%0], [%1], 16;" :: "r"(d), "l"(s))
#define CP_COMMIT()      asm volatile("cp.async.commit_group;" ::: "memory")
#define CP_WAIT0()       asm volatile("cp.async.wait_group 0;" ::: "memory")

// ---------------- smem layout ----------------
#define RSTR 272
#define QTILE (128*RSTR)
#define KROWS (64*RSTR)
#define KVBUF (4*KROWS)
#define SKV0  (2*QTILE)
#define SMEM_ATTN (SKV0 + 2*KVBUF)     // 208896

// ---------------- prep: rotate + fp16 split ----------------
__global__ __launch_bounds__(256) void prep_qkv(const float* __restrict__ Q,
                                                const float* __restrict__ K,
                                                const float* __restrict__ V) {
    int h = blockIdx.y;
    int s = blockIdx.x * 8 + (threadIdx.x >> 5);
    if (s >= S_TOT) return;
    int lane = threadIdx.x & 31;
    int gq = orig_idx(s);
    size_t si = ((size_t)gq * NH + h) * HD + lane * 4;
    size_t o  = ((size_t)h * S_TOT + s) * HD + lane * 4;
    float4 qv = *(const float4*)(Q + si);
    float4 kv = *(const float4*)(K + si);
    float4 vv = *(const float4*)(V + si);
    u32 qh0 = pack2(qv.x, qv.y), qh1 = pack2(qv.z, qv.w);
    u32 kh0 = pack2(kv.x, kv.y), kh1 = pack2(kv.z, kv.w);
    u32 vh0 = pack2(vv.x, vv.y), vh1 = pack2(vv.z, vv.w);
    *(uint2*)(g_Qh + o) = make_uint2(qh0, qh1);
    *(uint2*)(g_Ql + o) = make_uint2(pack2lo(qv.x, qv.y, qh0), pack2lo(qv.z, qv.w, qh1));
    *(uint2*)(g_Kh + o) = make_uint2(kh0, kh1);
    *(uint2*)(g_Kl + o) = make_uint2(pack2lo(kv.x, kv.y, kh0), pack2lo(kv.z, kv.w, kh1));
    *(uint2*)(g_Vh + o) = make_uint2(vh0, vh1);
    *(uint2*)(g_Vl + o) = make_uint2(pack2lo(vv.x, vv.y, vh0), pack2lo(vv.z, vv.w, vh1));
}

// ---------------- async KV block load ----------------
__device__ __forceinline__ void kv_load(u32 kvb, int c0, int tid,
    const __half* kh, const __half* kl, const __half* vh, const __half* vl)
{
#pragma unroll
    for (int it = 0; it < 4; it++) {
        int idx = tid + it * 256;
        int row = idx >> 4, ch = idx & 15;
        size_t src = (size_t)min(c0 + row, S_TOT - 1) * HD + ch * 8;
        u32 dst = kvb + row * RSTR + ch * 16;
        CP_ASYNC16(dst,           kh + src);
        CP_ASYNC16(dst + KROWS,   kl + src);
        CP_ASYNC16(dst + 2*KROWS, vh + src);
        CP_ASYNC16(dst + 3*KROWS, vl + src);
    }
}

// ---------------- fused attention + ratio kernel ----------------
__global__ __launch_bounds__(256, 1)
void fused_kernel(float* __restrict__ O, float* __restrict__ ratio)
{
    extern __shared__ char sm[];
    const u32 sb  = smem_u32(sm);
    const int tid = threadIdx.x, w = tid >> 5, lane = tid & 31;
    const int g = lane >> 2, tg = lane & 3;

    if (blockIdx.x >= 306) {
        // ================= ratio path =================
        int e = blockIdx.x - 306;            // 0..35
        const int type = e / 18, head = (e / 9) & 1, rb = e % 9;
        const int r0 = rb * 128;
        const int stride = type ? 8 : 1;

        const __half* qh = g_Qh + (size_t)head * S_TOT * HD;
        const __half* ql = g_Ql + (size_t)head * S_TOT * HD;
        const __half* kh = g_Kh + (size_t)head * S_TOT * HD;
        const __half* kl = g_Kl + (size_t)head * S_TOT * HD;

#pragma unroll
        for (int it = 0; it < 8; it++) {
            int idx = tid + it * 256;
            int row = idx >> 4, ch = idx & 15;
            size_t src = (size_t)(min(r0 + row, PF - 1) * stride) * HD + ch * 8;
            int dst = row * RSTR + ch * 16;
            *(uint4*)(sm + dst)         = *(const uint4*)(qh + src);
            *(uint4*)(sm + QTILE + dst) = *(const uint4*)(ql + src);
        }

        const u32 aAddr = sb + (w * 16 + (lane & 15)) * RSTR + (lane >> 4) * 16;
        const u32 bAddr = sb + 2*QTILE + ((lane & 7) + ((lane >> 4) & 1) * 8) * RSTR
                        + ((lane >> 3) & 1) * 16;

        float totA = 0.f, winA = 0.f, totB = 0.f, winB = 0.f;
        const int rA = r0 + w * 16 + g, rB = rA + 8;

        for (int blk = 0; blk < 17; blk++) {
            const int c0 = blk * 64;
            __syncthreads();
#pragma unroll
            for (int it = 0; it < 4; it++) {
                int idx = tid + it * 256;
                int row = idx >> 4, ch = idx & 15;
                size_t src = (size_t)(min(c0 + row, PF - 1) * stride) * HD + ch * 8;
                int dst = 2*QTILE + row * RSTR + ch * 16;
                *(uint4*)(sm + dst)         = *(const uint4*)(kh + src);
                *(uint4*)(sm + dst + KROWS) = *(const uint4*)(kl + src);
            }
            __syncthreads();

            float s[8][4];
#pragma unroll
            for (int x = 0; x < 8; x++)
#pragma unroll
                for (int j = 0; j < 4; j++) s[x][j] = 0.f;
#pragma unroll
            for (int kc = 0; kc < 8; kc++) {
                u32 Ah[4], Al[4];
                ldsm4(Ah, aAddr + kc * 32);
                ldsm4(Al, aAddr + QTILE + kc * 32);
#pragma unroll
                for (int nb2 = 0; nb2 < 4; nb2++) {
                    u32 Bh[4], Bl[4];
                    u32 ba = bAddr + nb2 * (16 * RSTR) + kc * 32;
                    ldsm4(Bh, ba);
                    ldsm4(Bl, ba + KROWS);
                    mma(s[2*nb2],   Ah, Bh[0], Bh[1]);
                    mma(s[2*nb2],   Ah, Bl[0], Bl[1]);
                    mma(s[2*nb2],   Al, Bh[0], Bh[1]);
                    mma(s[2*nb2+1], Ah, Bh[2], Bh[3]);
                    mma(s[2*nb2+1], Ah, Bl[2], Bl[3]);
                    mma(s[2*nb2+1], Al, Bh[2], Bh[3]);
                }
            }
#pragma unroll
            for (int nb = 0; nb < 8; nb++) {
                int c = c0 + nb * 8 + 2 * tg;
#pragma unroll
                for (int v = 0; v < 4; v++) {
                    int cc = c + (v & 1);
                    int rr = (v < 2) ? rA : rB;
                    float p = (cc < PF) ? __expf(s[nb][v] * SCALE) : 0.f;
                    if (v < 2) { totA += p; if (abs(rr - cc) <= WIN) winA += p; }
                    else       { totB += p; if (abs(rr - cc) <= WIN) winB += p; }
                }
            }
        }

        totA += __shfl_xor_sync(0xffffffffu, totA, 1);
        totA += __shfl_xor_sync(0xffffffffu, totA, 2);
        winA += __shfl_xor_sync(0xffffffffu, winA, 1);
        winA += __shfl_xor_sync(0xffffffffu, winA, 2);
        totB += __shfl_xor_sync(0xffffffffu, totB, 1);
        totB += __shfl_xor_sync(0xffffffffu, totB, 2);
        winB += __shfl_xor_sync(0xffffffffu, winB, 1);
        winB += __shfl_xor_sync(0xffffffffu, winB, 2);

        float* red = (float*)sm;
        __syncthreads();
        if (tid == 0) red[0] = 0.f;
        __syncthreads();
        if (tg == 0) {
            float contrib = 0.f;
            if (rA < PF) contrib += winA / totA;
            if (rB < PF) contrib += winB / totB;
            if (contrib != 0.f) atomicAdd(red, contrib);
        }
        __syncthreads();
        if (tid == 0) atomicAdd(&ratio[type * NH + head], red[0] * (1.f / (float)PF));
        return;
    }

    // ================= attention path =================
    int tile, head, chunk = -1, eidx = 0;
    int lo0, hi0, lo1, hi1;
    if (blockIdx.x < 130) {
        tile = blockIdx.x >> 1; head = blockIdx.x & 1;
        lo0 = max(0, 2*tile - 32); hi0 = min(129, 2*tile + 33);
        lo1 = 130; hi1 = 150;
    } else {
        int e = blockIdx.x - 130;
        int tileIdx = e >> 4; head = (e >> 3) & 1; chunk = e & 7;
        tile = 65 + tileIdx;
        eidx = e;
        lo0 = chunk * 19; hi0 = min(150, chunk * 19 + 18);
        lo1 = 0; hi1 = -1;
    }
    const int r0 = tile * 128;
    const bool rowRazor = (tile < 65);
    const int n0 = hi0 - lo0 + 1;
    const int nb_total = n0 + (hi1 >= lo1 ? hi1 - lo1 + 1 : 0);

    const __half* qh = g_Qh + (size_t)head * S_TOT * HD;
    const __half* ql = g_Ql + (size_t)head * S_TOT * HD;
    const __half* kh = g_Kh + (size_t)head * S_TOT * HD;
    const __half* kl = g_Kl + (size_t)head * S_TOT * HD;
    const __half* vh = g_Vh + (size_t)head * S_TOT * HD;
    const __half* vl = g_Vl + (size_t)head * S_TOT * HD;

    kv_load(sb + SKV0, lo0 * 64, tid, kh, kl, vh, vl);
    CP_COMMIT();

#pragma unroll
    for (int it = 0; it < 8; it++) {
        int idx = tid + it * 256;
        int row = idx >> 4, ch = idx & 15;
        size_t src = (size_t)min(r0 + row, S_TOT - 1) * HD + ch * 8;
        int dst = row * RSTR + ch * 16;
        *(uint4*)(sm + dst)         = *(const uint4*)(qh + src);
        *(uint4*)(sm + QTILE + dst) = *(const uint4*)(ql + src);
    }

    const u32 aAddr = sb + (w * 16 + (lane & 15)) * RSTR + (lane >> 4) * 16;
    const u32 offBK = ((lane & 7) + ((lane >> 4) & 1) * 8) * RSTR + ((lane >> 3) & 1) * 16;
    const u32 offBV = 2*KROWS + ((lane & 7) + ((lane >> 3) & 1) * 8) * RSTR + ((lane >> 4) & 1) * 16;

    float o[16][4];
#pragma unroll
    for (int i = 0; i < 16; i++)
#pragma unroll
        for (int j = 0; j < 4; j++) o[i][j] = 0.f;
    float laccA = 0.f, laccB = 0.f;
    const int rA = r0 + w * 16 + g, rB = rA + 8;

    for (int i = 0; i < nb_total; i++) {
        const int blk = (i < n0) ? lo0 + i : lo1 + (i - n0);
        const int c0 = blk * 64;
        int maskMode = 0;
        if (blk < 130) { if (rowRazor && (blk < 2*tile - 30 || blk > 2*tile + 31)) maskMode = 1; }
        else if (blk == 150) maskMode = 2;

        CP_WAIT0();
        __syncthreads();
        if (i + 1 < nb_total) {
            const int nblk = (i + 1 < n0) ? lo0 + i + 1 : lo1 + (i + 1 - n0);
            kv_load(sb + SKV0 + ((i + 1) & 1) * KVBUF, nblk * 64, tid, kh, kl, vh, vl);
            CP_COMMIT();
        }
        const u32 kvb = sb + SKV0 + (i & 1) * KVBUF;

        // ---- QK: S = QhKh + QhKl + QlKh (fp16 3-split) ----
        float s[8][4];
#pragma unroll
        for (int x = 0; x < 8; x++)
#pragma unroll
            for (int j = 0; j < 4; j++) s[x][j] = 0.f;

#pragma unroll
        for (int kc = 0; kc < 8; kc++) {
            u32 Ah[4], Al[4];
            ldsm4(Ah, aAddr + kc * 32);
            ldsm4(Al, aAddr + QTILE + kc * 32);
#pragma unroll
            for (int nb2 = 0; nb2 < 4; nb2++) {
                u32 Bh[4], Bl[4];
                u32 ba = kvb + offBK + nb2 * (16 * RSTR) + kc * 32;
                ldsm4(Bh, ba);
                ldsm4(Bl, ba + KROWS);
                mma(s[2*nb2],   Ah, Bh[0], Bh[1]);
                mma(s[2*nb2],   Ah, Bl[0], Bl[1]);
                mma(s[2*nb2],   Al, Bh[0], Bh[1]);
                mma(s[2*nb2+1], Ah, Bh[2], Bh[3]);
                mma(s[2*nb2+1], Ah, Bl[2], Bl[3]);
                mma(s[2*nb2+1], Al, Bh[2], Bh[3]);
            }
        }

        // ---- epilogue: mask + exp + fp16 pack (hi only) ----
        u32 ph[8][2];
#pragma unroll
        for (int nb = 0; nb < 8; nb++) {
            int c = c0 + nb * 8 + 2 * tg;
            float p00 = __expf(s[nb][0] * SCALE);
            float p01 = __expf(s[nb][1] * SCALE);
            float p10 = __expf(s[nb][2] * SCALE);
            float p11 = __expf(s[nb][3] * SCALE);
            if (maskMode == 1) {
                if ((unsigned)(c     - (rA - PRE)) > 2u*PRE) p00 = 0.f;
                if ((unsigned)(c + 1 - (rA - PRE)) > 2u*PRE) p01 = 0.f;
                if ((unsigned)(c     - (rB - PRE)) > 2u*PRE) p10 = 0.f;
                if ((unsigned)(c + 1 - (rB - PRE)) > 2u*PRE) p11 = 0.f;
            } else if (maskMode == 2) {
                if (c     >= S_TOT) { p00 = 0.f; p10 = 0.f; }
                if (c + 1 >= S_TOT) { p01 = 0.f; p11 = 0.f; }
            }
            laccA += p00 + p01;
            laccB += p10 + p11;
            ph[nb][0] = pack2(p00, p01);
            ph[nb][1] = pack2(p10, p11);
        }

        // ---- PV: O += P(Vh + Vl), P fp16 single ----
#pragma unroll
        for (int kc = 0; kc < 4; kc++) {
            u32 Ah[4] = { ph[2*kc][0], ph[2*kc][1], ph[2*kc+1][0], ph[2*kc+1][1] };
#pragma unroll
            for (int nb2 = 0; nb2 < 8; nb2++) {
                u32 Bh[4], Bl[4];
                u32 ba = kvb + offBV + kc * (16 * RSTR) + nb2 * 32;
                ldsm4t(Bh, ba);
                ldsm4t(Bl, ba + KROWS);
                mma(o[2*nb2],   Ah, Bh[0], Bh[1]);
                mma(o[2*nb2],   Ah, Bl[0], Bl[1]);
                mma(o[2*nb2+1], Ah, Bh[2], Bh[3]);
                mma(o[2*nb2+1], Ah, Bl[2], Bl[3]);
            }
        }
    }

    // ---- finalize ----
    laccA += __shfl_xor_sync(0xffffffffu, laccA, 1);
    laccA += __shfl_xor_sync(0xffffffffu, laccA, 2);
    laccB += __shfl_xor_sync(0xffffffffu, laccB, 1);
    laccB += __shfl_xor_sync(0xffffffffu, laccB, 2);

    if (chunk < 0) {
        float invA = 1.f / laccA, invB = 1.f / laccB;
        if (rA < S_TOT) {
            float* base = O + ((size_t)orig_idx(rA) * NH + head) * HD;
#pragma unroll
            for (int nb = 0; nb < 16; nb++)
                *(float2*)(base + nb * 8 + 2 * tg) = make_float2(o[nb][0] * invA, o[nb][1] * invA);
        }
        if (rB < S_TOT) {
            float* base = O + ((size_t)orig_idx(rB) * NH + head) * HD;
#pragma unroll
            for (int nb = 0; nb < 16; nb++)
                *(float2*)(base + nb * 8 + 2 * tg) = make_float2(o[nb][2] * invB, o[nb][3] * invB);
        }
    } else {
        float* so = g_scrO + (size_t)eidx * 16384;
        int rlA = w * 16 + g, rlB = rlA + 8;
#pragma unroll
        for (int nb = 0; nb < 16; nb++) {
            *(float2*)(so + rlA * 128 + nb * 8 + 2 * tg) = make_float2(o[nb][0], o[nb][1]);
            *(float2*)(so + rlB * 128 + nb * 8 + 2 * tg) = make_float2(o[nb][2], o[nb][3]);
        }
        if (tg == 0) {
            g_scrL[eidx * 128 + rlA] = laccA;
            g_scrL[eidx * 128 + rlB] = laccB;
        }
    }
}

// ---------------- combine tail partials ----------------
__global__ __launch_bounds__(256) void combine_kernel(float* __restrict__ O) {
    int b = blockIdx.x;
    int tileIdx = b >> 1, head = b & 1;
    int tile = 65 + tileIdx, r0 = tile * 128;
    int ebase = tileIdx * 16 + head * 8;
    int tid = threadIdx.x;

    __shared__ float ls[128];
    if (tid < 128) {
        float sum = 0.f;
#pragma unroll
        for (int c = 0; c < NCHUNK; c++) sum += g_scrL[(ebase + c) * 128 + tid];
        ls[tid] = 1.f / sum;
    }
    __syncthreads();

    for (int k = tid; k < 16384; k += 256) {
        int row = k >> 7, col = k & 127;
        if (r0 + row >= S_TOT) continue;
        float sum = 0.f;
#pragma unroll
        for (int c = 0; c < NCHUNK; c++) sum += g_scrO[(size_t)(ebase + c) * 16384 + k];
        int gr = orig_idx(r0 + row);
        O[((size_t)gr * NH + head) * HD + col] = sum * ls[row];
    }
}

__global__ void zero_ratio(float* r) {
    if (threadIdx.x < 4) r[threadIdx.x] = 0.f;
}

// ---------------- launch ----------------
extern "C" void kernel_launch(void* const* d_in, const int* in_sizes, int n_in,
                              void* d_out, int out_size)
{
    const float* Q = (const float*)d_in[0];
    const float* K = (const float*)d_in[1];
    const float* V = (const float*)d_in[2];
    float* O     = (float*)d_out;
    float* ratio = O + (size_t)S_TOT * NH * HD;

    cudaFuncSetAttribute(fused_kernel, cudaFuncAttributeMaxDynamicSharedMemorySize, SMEM_ATTN);

    zero_ratio<<<1, 32>>>(ratio);
    prep_qkv<<<dim3(1202, NH), 256>>>(Q, K, V);
    fused_kernel<<<342, 256, SMEM_ATTN>>>(O, ratio);
    combine_kernel<<<22, 256>>>(O);
}

// round 8
// speedup vs baseline: 8.4023x; 1.3090x over previous
#include <cuda_runtime.h>
#include <cuda_fp16.h>
#include <math.h>

typedef unsigned int u32;

// ---------------- problem constants ----------------
#define S_TOT 9616
#define RAZOR 8320
#define PF    1040
#define ROT   8576
#define NH    2
#define HD    128
#define PRE   2048
#define WIN   301
#define SCALE 0.08838834764831845f

// rotated fp16 split buffers [h][s][d]
__device__ __half g_Qh[(size_t)NH*S_TOT*HD];
__device__ __half g_Ql[(size_t)NH*S_TOT*HD];
__device__ __half g_Kh[(size_t)NH*S_TOT*HD];
__device__ __half g_Kl[(size_t)NH*S_TOT*HD];
__device__ __half g_Vh[(size_t)NH*S_TOT*HD];

// tail-tile partial scratch: 11 tiles x 2 heads x 8 chunks
#define NCHUNK 8
__device__ float g_scrO[(size_t)11*2*NCHUNK*128*128];
__device__ float g_scrL[(size_t)11*2*NCHUNK*128];

__device__ __forceinline__ int orig_idx(int r) { return r < ROT ? r + PF : r - ROT; }

__device__ __forceinline__ u32 smem_u32(const void* p) {
    u32 a;
    asm("{ .reg .u64 t; cvta.to.shared.u64 t, %1; cvt.u32.u64 %0, t; }" : "=r"(a) : "l"(p));
    return a;
}
__device__ __forceinline__ void ldsm4(u32* r, u32 a) {
    asm volatile("ldmatrix.sync.aligned.m8n8.x4.shared.b16 {%0,%1,%2,%3}, [%4];"
                 : "=r"(r[0]), "=r"(r[1]), "=r"(r[2]), "=r"(r[3]) : "r"(a));
}
__device__ __forceinline__ void ldsm4t(u32* r, u32 a) {
    asm volatile("ldmatrix.sync.aligned.m8n8.x4.trans.shared.b16 {%0,%1,%2,%3}, [%4];"
                 : "=r"(r[0]), "=r"(r[1]), "=r"(r[2]), "=r"(r[3]) : "r"(a));
}
__device__ __forceinline__ void mma(float* d, const u32* a, u32 b0, u32 b1) {
    asm volatile("mma.sync.aligned.m16n8k16.row.col.f32.f16.f16.f32 "
                 "{%0,%1,%2,%3},{%4,%5,%6,%7},{%8,%9},{%0,%1,%2,%3};"
                 : "+f"(d[0]), "+f"(d[1]), "+f"(d[2]), "+f"(d[3])
                 : "r"(a[0]), "r"(a[1]), "r"(a[2]), "r"(a[3]), "r"(b0), "r"(b1));
}
__device__ __forceinline__ u32 pack2(float a, float b) {
    __half2 t = __floats2half2_rn(a, b);
    return *(u32*)&t;
}
__device__ __forceinline__ u32 pack2lo(float a, float b, u32 hipk) {
    __half2 h = *(__half2*)&hipk;
    return pack2(a - __half2float(h.x), b - __half2float(h.y));
}

#define CP_ASYNC16(d, s) asm volatile("cp.async.cg.shared.global [%0], [%1], 16;" :: "r"(d), "l"(s))
#define CP_COMMIT()      asm volatile("cp.async.commit_group;" ::: "memory")
#define CP_WAIT0()       asm volatile("cp.async.wait_group 0;" ::: "memory")

// ---------------- smem layout ----------------
#define RSTR 272
#define QTILE (128*RSTR)               // 34816
#define KROWS (64*RSTR)                // 17408
#define KVBUF (3*KROWS)                // 52224: [KH|KL|VH]
#define SKV0  (2*QTILE)                // 69632
#define SMEM_ATTN (SKV0 + 2*KVBUF)     // 174080

// ---------------- prep: rotate + fp16 split ----------------
__global__ __launch_bounds__(256) void prep_qkv(const float* __restrict__ Q,
                                                const float* __restrict__ K,
                                                const float* __restrict__ V) {
    int h = blockIdx.y;
    int s = blockIdx.x * 8 + (threadIdx.x >> 5);
    if (s >= S_TOT) return;
    int lane = threadIdx.x & 31;
    int gq = orig_idx(s);
    size_t si = ((size_t)gq * NH + h) * HD + lane * 4;
    size_t o  = ((size_t)h * S_TOT + s) * HD + lane * 4;
    float4 qv = *(const float4*)(Q + si);
    float4 kv = *(const float4*)(K + si);
    float4 vv = *(const float4*)(V + si);
    u32 qh0 = pack2(qv.x, qv.y), qh1 = pack2(qv.z, qv.w);
    u32 kh0 = pack2(kv.x, kv.y), kh1 = pack2(kv.z, kv.w);
    *(uint2*)(g_Qh + o) = make_uint2(qh0, qh1);
    *(uint2*)(g_Ql + o) = make_uint2(pack2lo(qv.x, qv.y, qh0), pack2lo(qv.z, qv.w, qh1));
    *(uint2*)(g_Kh + o) = make_uint2(kh0, kh1);
    *(uint2*)(g_Kl + o) = make_uint2(pack2lo(kv.x, kv.y, kh0), pack2lo(kv.z, kv.w, kh1));
    *(uint2*)(g_Vh + o) = make_uint2(pack2(vv.x, vv.y), pack2(vv.z, vv.w));
}

// ---------------- async KV block load (Kh, Kl, Vh) ----------------
__device__ __forceinline__ void kv_load(u32 kvb, int c0, int tid,
    const __half* kh, const __half* kl, const __half* vh)
{
#pragma unroll
    for (int it = 0; it < 4; it++) {
        int idx = tid + it * 256;
        int row = idx >> 4, ch = idx & 15;
        size_t src = (size_t)min(c0 + row, S_TOT - 1) * HD + ch * 8;
        u32 dst = kvb + row * RSTR + ch * 16;
        CP_ASYNC16(dst,           kh + src);
        CP_ASYNC16(dst + KROWS,   kl + src);
        CP_ASYNC16(dst + 2*KROWS, vh + src);
    }
}

// ---------------- fused attention + ratio kernel ----------------
__global__ __launch_bounds__(256, 1)
void fused_kernel(float* __restrict__ O, float* __restrict__ ratio)
{
    extern __shared__ char sm[];
    const u32 sb  = smem_u32(sm);
    const int tid = threadIdx.x, w = tid >> 5, lane = tid & 31;
    const int g = lane >> 2, tg = lane & 3;

    if (blockIdx.x >= 306) {
        // ================= ratio path =================
        int e = blockIdx.x - 306;            // 0..35
        const int type = e / 18, head = (e / 9) & 1, rb = e % 9;
        const int r0 = rb * 128;
        const int stride = type ? 8 : 1;

        const __half* qh = g_Qh + (size_t)head * S_TOT * HD;
        const __half* ql = g_Ql + (size_t)head * S_TOT * HD;
        const __half* kh = g_Kh + (size_t)head * S_TOT * HD;
        const __half* kl = g_Kl + (size_t)head * S_TOT * HD;

#pragma unroll
        for (int it = 0; it < 8; it++) {
            int idx = tid + it * 256;
            int row = idx >> 4, ch = idx & 15;
            size_t src = (size_t)(min(r0 + row, PF - 1) * stride) * HD + ch * 8;
            int dst = row * RSTR + ch * 16;
            *(uint4*)(sm + dst)         = *(const uint4*)(qh + src);
            *(uint4*)(sm + QTILE + dst) = *(const uint4*)(ql + src);
        }

        const u32 aAddr = sb + (w * 16 + (lane & 15)) * RSTR + (lane >> 4) * 16;
        const u32 bAddr = sb + 2*QTILE + ((lane & 7) + ((lane >> 4) & 1) * 8) * RSTR
                        + ((lane >> 3) & 1) * 16;

        float totA = 0.f, winA = 0.f, totB = 0.f, winB = 0.f;
        const int rA = r0 + w * 16 + g, rB = rA + 8;

        for (int blk = 0; blk < 17; blk++) {
            const int c0 = blk * 64;
            __syncthreads();
#pragma unroll
            for (int it = 0; it < 4; it++) {
                int idx = tid + it * 256;
                int row = idx >> 4, ch = idx & 15;
                size_t src = (size_t)(min(c0 + row, PF - 1) * stride) * HD + ch * 8;
                int dst = 2*QTILE + row * RSTR + ch * 16;
                *(uint4*)(sm + dst)         = *(const uint4*)(kh + src);
                *(uint4*)(sm + dst + KROWS) = *(const uint4*)(kl + src);
            }
            __syncthreads();

            float s[8][4];
#pragma unroll
            for (int x = 0; x < 8; x++)
#pragma unroll
                for (int j = 0; j < 4; j++) s[x][j] = 0.f;
#pragma unroll
            for (int kc = 0; kc < 8; kc++) {
                u32 Ah[4], Al[4];
                ldsm4(Ah, aAddr + kc * 32);
                ldsm4(Al, aAddr + QTILE + kc * 32);
#pragma unroll
                for (int nb2 = 0; nb2 < 4; nb2++) {
                    u32 Bh[4], Bl[4];
                    u32 ba = bAddr + nb2 * (16 * RSTR) + kc * 32;
                    ldsm4(Bh, ba);
                    ldsm4(Bl, ba + KROWS);
                    mma(s[2*nb2],   Ah, Bh[0], Bh[1]);
                    mma(s[2*nb2],   Ah, Bl[0], Bl[1]);
                    mma(s[2*nb2],   Al, Bh[0], Bh[1]);
                    mma(s[2*nb2+1], Ah, Bh[2], Bh[3]);
                    mma(s[2*nb2+1], Ah, Bl[2], Bl[3]);
                    mma(s[2*nb2+1], Al, Bh[2], Bh[3]);
                }
            }
#pragma unroll
            for (int nb = 0; nb < 8; nb++) {
                int c = c0 + nb * 8 + 2 * tg;
#pragma unroll
                for (int v = 0; v < 4; v++) {
                    int cc = c + (v & 1);
                    int rr = (v < 2) ? rA : rB;
                    float p = (cc < PF) ? __expf(s[nb][v] * SCALE) : 0.f;
                    if (v < 2) { totA += p; if (abs(rr - cc) <= WIN) winA += p; }
                    else       { totB += p; if (abs(rr - cc) <= WIN) winB += p; }
                }
            }
        }

        totA += __shfl_xor_sync(0xffffffffu, totA, 1);
        totA += __shfl_xor_sync(0xffffffffu, totA, 2);
        winA += __shfl_xor_sync(0xffffffffu, winA, 1);
        winA += __shfl_xor_sync(0xffffffffu, winA, 2);
        totB += __shfl_xor_sync(0xffffffffu, totB, 1);
        totB += __shfl_xor_sync(0xffffffffu, totB, 2);
        winB += __shfl_xor_sync(0xffffffffu, winB, 1);
        winB += __shfl_xor_sync(0xffffffffu, winB, 2);

        float* red = (float*)sm;
        __syncthreads();
        if (tid == 0) red[0] = 0.f;
        __syncthreads();
        if (tg == 0) {
            float contrib = 0.f;
            if (rA < PF) contrib += winA / totA;
            if (rB < PF) contrib += winB / totB;
            if (contrib != 0.f) atomicAdd(red, contrib);
        }
        __syncthreads();
        if (tid == 0) atomicAdd(&ratio[type * NH + head], red[0] * (1.f / (float)PF));
        return;
    }

    // ================= attention path =================
    int tile, head, chunk = -1, eidx = 0;
    int lo0, hi0, lo1, hi1;
    if (blockIdx.x < 130) {
        tile = blockIdx.x >> 1; head = blockIdx.x & 1;
        lo0 = max(0, 2*tile - 32); hi0 = min(129, 2*tile + 33);
        lo1 = 130; hi1 = 150;
    } else {
        int e = blockIdx.x - 130;
        int tileIdx = e >> 4; head = (e >> 3) & 1; chunk = e & 7;
        tile = 65 + tileIdx;
        eidx = e;
        lo0 = chunk * 19; hi0 = min(150, chunk * 19 + 18);
        lo1 = 0; hi1 = -1;
    }
    const int r0 = tile * 128;
    const bool rowRazor = (tile < 65);
    const int n0 = hi0 - lo0 + 1;
    const int nb_total = n0 + (hi1 >= lo1 ? hi1 - lo1 + 1 : 0);

    const __half* qh = g_Qh + (size_t)head * S_TOT * HD;
    const __half* ql = g_Ql + (size_t)head * S_TOT * HD;
    const __half* kh = g_Kh + (size_t)head * S_TOT * HD;
    const __half* kl = g_Kl + (size_t)head * S_TOT * HD;
    const __half* vh = g_Vh + (size_t)head * S_TOT * HD;

    kv_load(sb + SKV0, lo0 * 64, tid, kh, kl, vh);
    CP_COMMIT();

#pragma unroll
    for (int it = 0; it < 8; it++) {
        int idx = tid + it * 256;
        int row = idx >> 4, ch = idx & 15;
        size_t src = (size_t)min(r0 + row, S_TOT - 1) * HD + ch * 8;
        int dst = row * RSTR + ch * 16;
        *(uint4*)(sm + dst)         = *(const uint4*)(qh + src);
        *(uint4*)(sm + QTILE + dst) = *(const uint4*)(ql + src);
    }

    const u32 aAddr = sb + (w * 16 + (lane & 15)) * RSTR + (lane >> 4) * 16;
    const u32 offBK = ((lane & 7) + ((lane >> 4) & 1) * 8) * RSTR + ((lane >> 3) & 1) * 16;
    const u32 offBV = 2*KROWS + ((lane & 7) + ((lane >> 3) & 1) * 8) * RSTR + ((lane >> 4) & 1) * 16;

    float o[16][4];
#pragma unroll
    for (int i = 0; i < 16; i++)
#pragma unroll
        for (int j = 0; j < 4; j++) o[i][j] = 0.f;
    float laccA = 0.f, laccB = 0.f;
    const int rA = r0 + w * 16 + g, rB = rA + 8;

    for (int i = 0; i < nb_total; i++) {
        const int blk = (i < n0) ? lo0 + i : lo1 + (i - n0);
        const int c0 = blk * 64;
        int maskMode = 0;
        if (blk < 130) { if (rowRazor && (blk < 2*tile - 30 || blk > 2*tile + 31)) maskMode = 1; }
        else if (blk == 150) maskMode = 2;

        CP_WAIT0();
        __syncthreads();
        if (i + 1 < nb_total) {
            const int nblk = (i + 1 < n0) ? lo0 + i + 1 : lo1 + (i + 1 - n0);
            kv_load(sb + SKV0 + ((i + 1) & 1) * KVBUF, nblk * 64, tid, kh, kl, vh);
            CP_COMMIT();
        }
        const u32 kvb = sb + SKV0 + (i & 1) * KVBUF;

        // ---- QK: S = QhKh + QhKl + QlKh (fp16 3-split) ----
        float s[8][4];
#pragma unroll
        for (int x = 0; x < 8; x++)
#pragma unroll
            for (int j = 0; j < 4; j++) s[x][j] = 0.f;

#pragma unroll
        for (int kc = 0; kc < 8; kc++) {
            u32 Ah[4], Al[4];
            ldsm4(Ah, aAddr + kc * 32);
            ldsm4(Al, aAddr + QTILE + kc * 32);
#pragma unroll
            for (int nb2 = 0; nb2 < 4; nb2++) {
                u32 Bh[4], Bl[4];
                u32 ba = kvb + offBK + nb2 * (16 * RSTR) + kc * 32;
                ldsm4(Bh, ba);
                ldsm4(Bl, ba + KROWS);
                mma(s[2*nb2],   Ah, Bh[0], Bh[1]);
                mma(s[2*nb2],   Ah, Bl[0], Bl[1]);
                mma(s[2*nb2],   Al, Bh[0], Bh[1]);
                mma(s[2*nb2+1], Ah, Bh[2], Bh[3]);
                mma(s[2*nb2+1], Ah, Bl[2], Bl[3]);
                mma(s[2*nb2+1], Al, Bh[2], Bh[3]);
            }
        }

        // ---- epilogue: mask + exp + fp16 pack ----
        u32 ph[8][2];
#pragma unroll
        for (int nb = 0; nb < 8; nb++) {
            int c = c0 + nb * 8 + 2 * tg;
            float p00 = __expf(s[nb][0] * SCALE);
            float p01 = __expf(s[nb][1] * SCALE);
            float p10 = __expf(s[nb][2] * SCALE);
            float p11 = __expf(s[nb][3] * SCALE);
            if (maskMode == 1) {
                if ((unsigned)(c     - (rA - PRE)) > 2u*PRE) p00 = 0.f;
                if ((unsigned)(c + 1 - (rA - PRE)) > 2u*PRE) p01 = 0.f;
                if ((unsigned)(c     - (rB - PRE)) > 2u*PRE) p10 = 0.f;
                if ((unsigned)(c + 1 - (rB - PRE)) > 2u*PRE) p11 = 0.f;
            } else if (maskMode == 2) {
                if (c     >= S_TOT) { p00 = 0.f; p10 = 0.f; }
                if (c + 1 >= S_TOT) { p01 = 0.f; p11 = 0.f; }
            }
            laccA += p00 + p01;
            laccB += p10 + p11;
            ph[nb][0] = pack2(p00, p01);
            ph[nb][1] = pack2(p10, p11);
        }

        // ---- PV: O += P * Vh ----
#pragma unroll
        for (int kc = 0; kc < 4; kc++) {
            u32 Ah[4] = { ph[2*kc][0], ph[2*kc][1], ph[2*kc+1][0], ph[2*kc+1][1] };
#pragma unroll
            for (int nb2 = 0; nb2 < 8; nb2++) {
                u32 Bh[4];
                ldsm4t(Bh, kvb + offBV + kc * (16 * RSTR) + nb2 * 32);
                mma(o[2*nb2],   Ah, Bh[0], Bh[1]);
                mma(o[2*nb2+1], Ah, Bh[2], Bh[3]);
            }
        }
    }

    // ---- finalize ----
    laccA += __shfl_xor_sync(0xffffffffu, laccA, 1);
    laccA += __shfl_xor_sync(0xffffffffu, laccA, 2);
    laccB += __shfl_xor_sync(0xffffffffu, laccB, 1);
    laccB += __shfl_xor_sync(0xffffffffu, laccB, 2);

    if (chunk < 0) {
        float invA = 1.f / laccA, invB = 1.f / laccB;
        if (rA < S_TOT) {
            float* base = O + ((size_t)orig_idx(rA) * NH + head) * HD;
#pragma unroll
            for (int nb = 0; nb < 16; nb++)
                *(float2*)(base + nb * 8 + 2 * tg) = make_float2(o[nb][0] * invA, o[nb][1] * invA);
        }
        if (rB < S_TOT) {
            float* base = O + ((size_t)orig_idx(rB) * NH + head) * HD;
#pragma unroll
            for (int nb = 0; nb < 16; nb++)
                *(float2*)(base + nb * 8 + 2 * tg) = make_float2(o[nb][2] * invB, o[nb][3] * invB);
        }
    } else {
        float* so = g_scrO + (size_t)eidx * 16384;
        int rlA = w * 16 + g, rlB = rlA + 8;
#pragma unroll
        for (int nb = 0; nb < 16; nb++) {
            *(float2*)(so + rlA * 128 + nb * 8 + 2 * tg) = make_float2(o[nb][0], o[nb][1]);
            *(float2*)(so + rlB * 128 + nb * 8 + 2 * tg) = make_float2(o[nb][2], o[nb][3]);
        }
        if (tg == 0) {
            g_scrL[eidx * 128 + rlA] = laccA;
            g_scrL[eidx * 128 + rlB] = laccB;
        }
    }
}

// ---------------- combine tail partials (wide grid) ----------------
// grid 352 = 22 pairs x 16 slices; each block handles 1024 of 16384 elements
__global__ __launch_bounds__(256) void combine_kernel(float* __restrict__ O) {
    int pair  = blockIdx.x >> 4;          // 0..21
    int slice = blockIdx.x & 15;          // 0..15
    int tileIdx = pair >> 1, head = pair & 1;
    int tile = 65 + tileIdx, r0 = tile * 128;
    int ebase = tileIdx * 16 + head * 8;
    int tid = threadIdx.x;

    // rows covered by this slice: 8 rows (slice*8 .. slice*8+7)
    __shared__ float ls[8];
    if (tid < 8) {
        int row = slice * 8 + tid;
        float sum = 0.f;
#pragma unroll
        for (int c = 0; c < NCHUNK; c++) sum += g_scrL[(ebase + c) * 128 + row];
        ls[tid] = 1.f / sum;
    }
    __syncthreads();

#pragma unroll
    for (int r = 0; r < 4; r++) {
        int k = slice * 1024 + r * 256 + tid;    // element within 128x128 tile
        int row = k >> 7, col = k & 127;
        if (r0 + row >= S_TOT) continue;
        float sum = 0.f;
#pragma unroll
        for (int c = 0; c < NCHUNK; c++) sum += g_scrO[(size_t)(ebase + c) * 16384 + k];
        int gr = orig_idx(r0 + row);
        O[((size_t)gr * NH + head) * HD + col] = sum * ls[row - slice * 8];
    }
}

__global__ void zero_ratio(float* r) {
    if (threadIdx.x < 4) r[threadIdx.x] = 0.f;
}

// ---------------- launch ----------------
extern "C" void kernel_launch(void* const* d_in, const int* in_sizes, int n_in,
                              void* d_out, int out_size)
{
    const float* Q = (const float*)d_in[0];
    const float* K = (const float*)d_in[1];
    const float* V = (const float*)d_in[2];
    float* O     = (float*)d_out;
    float* ratio = O + (size_t)S_TOT * NH * HD;

    cudaFuncSetAttribute(fused_kernel, cudaFuncAttributeMaxDynamicSharedMemorySize, SMEM_ATTN);

    zero_ratio<<<1, 32>>>(ratio);
    prep_qkv<<<dim3(1202, NH), 256>>>(Q, K, V);
    fused_kernel<<<342, 256, SMEM_ATTN>>>(O, ratio);
    combine_kernel<<<352, 256>>>(O);
}

// round 9
// speedup vs baseline: 9.4955x; 1.1301x over previous
#include <cuda_runtime.h>
#include <cuda_fp16.h>
#include <math.h>

typedef unsigned int u32;

// ---------------- problem constants ----------------
#define S_TOT 9616
#define RAZOR 8320
#define PF    1040
#define ROT   8576
#define NH    2
#define HD    128
#define PRE   2048
#define WIN   301
#define SCALE 0.08838834764831845f

// rotated fp16 split buffers [h][s][d]
__device__ __half g_Qh[(size_t)NH*S_TOT*HD];
__device__ __half g_Kh[(size_t)NH*S_TOT*HD];
__device__ __half g_Kl[(size_t)NH*S_TOT*HD];
__device__ __half g_Vh[(size_t)NH*S_TOT*HD];

// tail-tile partial scratch: 11 tiles x 2 heads x 8 chunks
#define NCHUNK 8
__device__ float g_scrO[(size_t)11*2*NCHUNK*128*128];
__device__ float g_scrL[(size_t)11*2*NCHUNK*128];

__device__ __forceinline__ int orig_idx(int r) { return r < ROT ? r + PF : r - ROT; }

__device__ __forceinline__ u32 smem_u32(const void* p) {
    u32 a;
    asm("{ .reg .u64 t; cvta.to.shared.u64 t, %1; cvt.u32.u64 %0, t; }" : "=r"(a) : "l"(p));
    return a;
}
__device__ __forceinline__ void ldsm4(u32* r, u32 a) {
    asm volatile("ldmatrix.sync.aligned.m8n8.x4.shared.b16 {%0,%1,%2,%3}, [%4];"
                 : "=r"(r[0]), "=r"(r[1]), "=r"(r[2]), "=r"(r[3]) : "r"(a));
}
__device__ __forceinline__ void ldsm4t(u32* r, u32 a) {
    asm volatile("ldmatrix.sync.aligned.m8n8.x4.trans.shared.b16 {%0,%1,%2,%3}, [%4];"
                 : "=r"(r[0]), "=r"(r[1]), "=r"(r[2]), "=r"(r[3]) : "r"(a));
}
__device__ __forceinline__ void mma(float* d, const u32* a, u32 b0, u32 b1) {
    asm volatile("mma.sync.aligned.m16n8k16.row.col.f32.f16.f16.f32 "
                 "{%0,%1,%2,%3},{%4,%5,%6,%7},{%8,%9},{%0,%1,%2,%3};"
                 : "+f"(d[0]), "+f"(d[1]), "+f"(d[2]), "+f"(d[3])
                 : "r"(a[0]), "r"(a[1]), "r"(a[2]), "r"(a[3]), "r"(b0), "r"(b1));
}
__device__ __forceinline__ u32 pack2(float a, float b) {
    __half2 t = __floats2half2_rn(a, b);
    return *(u32*)&t;
}
__device__ __forceinline__ u32 pack2lo(float a, float b, u32 hipk) {
    __half2 h = *(__half2*)&hipk;
    return pack2(a - __half2float(h.x), b - __half2float(h.y));
}

#define CP_ASYNC16(d, s) asm volatile("cp.async.cg.shared.global [%0], [%1], 16;" :: "r"(d), "l"(s))
#define CP_COMMIT()      asm volatile("cp.async.commit_group;" ::: "memory")
#define CP_WAIT1()       asm volatile("cp.async.wait_group 1;" ::: "memory")

// ---------------- smem layout ----------------
#define RSTR 272
#define QTILE (128*RSTR)               // 34816 (Qh only)
#define KROWS (64*RSTR)                // 17408
#define KVBUF (3*KROWS)                // 52224: [KH|KL|VH]
#define SKV0  QTILE                    // 34816
#define SMEM_ATTN (SKV0 + 3*KVBUF)     // 191488

// ---------------- prep: rotate + fp16 split ----------------
__global__ __launch_bounds__(256) void prep_qkv(const float* __restrict__ Q,
                                                const float* __restrict__ K,
                                                const float* __restrict__ V) {
    int h = blockIdx.y;
    int s = blockIdx.x * 8 + (threadIdx.x >> 5);
    if (s >= S_TOT) return;
    int lane = threadIdx.x & 31;
    int gq = orig_idx(s);
    size_t si = ((size_t)gq * NH + h) * HD + lane * 4;
    size_t o  = ((size_t)h * S_TOT + s) * HD + lane * 4;
    float4 qv = *(const float4*)(Q + si);
    float4 kv = *(const float4*)(K + si);
    float4 vv = *(const float4*)(V + si);
    u32 kh0 = pack2(kv.x, kv.y), kh1 = pack2(kv.z, kv.w);
    *(uint2*)(g_Qh + o) = make_uint2(pack2(qv.x, qv.y), pack2(qv.z, qv.w));
    *(uint2*)(g_Kh + o) = make_uint2(kh0, kh1);
    *(uint2*)(g_Kl + o) = make_uint2(pack2lo(kv.x, kv.y, kh0), pack2lo(kv.z, kv.w, kh1));
    *(uint2*)(g_Vh + o) = make_uint2(pack2(vv.x, vv.y), pack2(vv.z, vv.w));
}

// ---------------- async KV block load (Kh, Kl, Vh) ----------------
__device__ __forceinline__ void kv_load(u32 kvb, int c0, int tid,
    const __half* kh, const __half* kl, const __half* vh)
{
#pragma unroll
    for (int it = 0; it < 4; it++) {
        int idx = tid + it * 256;
        int row = idx >> 4, ch = idx & 15;
        size_t src = (size_t)min(c0 + row, S_TOT - 1) * HD + ch * 8;
        u32 dst = kvb + row * RSTR + ch * 16;
        CP_ASYNC16(dst,           kh + src);
        CP_ASYNC16(dst + KROWS,   kl + src);
        CP_ASYNC16(dst + 2*KROWS, vh + src);
    }
}

// ---------------- fused attention + ratio kernel ----------------
__global__ __launch_bounds__(256, 1)
void fused_kernel(float* __restrict__ O, float* __restrict__ ratio)
{
    extern __shared__ char sm[];
    const u32 sb  = smem_u32(sm);
    const int tid = threadIdx.x, w = tid >> 5, lane = tid & 31;
    const int g = lane >> 2, tg = lane & 3;

    if (blockIdx.x >= 306) {
        // ================= ratio path (2-split QK) =================
        int e = blockIdx.x - 306;            // 0..35
        const int type = e / 18, head = (e / 9) & 1, rb = e % 9;
        const int r0 = rb * 128;
        const int stride = type ? 8 : 1;

        const __half* qh = g_Qh + (size_t)head * S_TOT * HD;
        const __half* kh = g_Kh + (size_t)head * S_TOT * HD;
        const __half* kl = g_Kl + (size_t)head * S_TOT * HD;

#pragma unroll
        for (int it = 0; it < 8; it++) {
            int idx = tid + it * 256;
            int row = idx >> 4, ch = idx & 15;
            size_t src = (size_t)(min(r0 + row, PF - 1) * stride) * HD + ch * 8;
            *(uint4*)(sm + row * RSTR + ch * 16) = *(const uint4*)(qh + src);
        }

        const u32 aAddr = sb + (w * 16 + (lane & 15)) * RSTR + (lane >> 4) * 16;
        const u32 bAddr = sb + QTILE + ((lane & 7) + ((lane >> 4) & 1) * 8) * RSTR
                        + ((lane >> 3) & 1) * 16;

        float totA = 0.f, winA = 0.f, totB = 0.f, winB = 0.f;
        const int rA = r0 + w * 16 + g, rB = rA + 8;

        for (int blk = 0; blk < 17; blk++) {
            const int c0 = blk * 64;
            __syncthreads();
#pragma unroll
            for (int it = 0; it < 4; it++) {
                int idx = tid + it * 256;
                int row = idx >> 4, ch = idx & 15;
                size_t src = (size_t)(min(c0 + row, PF - 1) * stride) * HD + ch * 8;
                int dst = QTILE + row * RSTR + ch * 16;
                *(uint4*)(sm + dst)         = *(const uint4*)(kh + src);
                *(uint4*)(sm + dst + KROWS) = *(const uint4*)(kl + src);
            }
            __syncthreads();

            float s[8][4];
#pragma unroll
            for (int x = 0; x < 8; x++)
#pragma unroll
                for (int j = 0; j < 4; j++) s[x][j] = 0.f;
#pragma unroll
            for (int kc = 0; kc < 8; kc++) {
                u32 Ah[4];
                ldsm4(Ah, aAddr + kc * 32);
#pragma unroll
                for (int nb2 = 0; nb2 < 4; nb2++) {
                    u32 Bh[4], Bl[4];
                    u32 ba = bAddr + nb2 * (16 * RSTR) + kc * 32;
                    ldsm4(Bh, ba);
                    ldsm4(Bl, ba + KROWS);
                    mma(s[2*nb2],   Ah, Bh[0], Bh[1]);
                    mma(s[2*nb2],   Ah, Bl[0], Bl[1]);
                    mma(s[2*nb2+1], Ah, Bh[2], Bh[3]);
                    mma(s[2*nb2+1], Ah, Bl[2], Bl[3]);
                }
            }
#pragma unroll
            for (int nb = 0; nb < 8; nb++) {
                int c = c0 + nb * 8 + 2 * tg;
#pragma unroll
                for (int v = 0; v < 4; v++) {
                    int cc = c + (v & 1);
                    int rr = (v < 2) ? rA : rB;
                    float p = (cc < PF) ? __expf(s[nb][v] * SCALE) : 0.f;
                    if (v < 2) { totA += p; if (abs(rr - cc) <= WIN) winA += p; }
                    else       { totB += p; if (abs(rr - cc) <= WIN) winB += p; }
                }
            }
        }

        totA += __shfl_xor_sync(0xffffffffu, totA, 1);
        totA += __shfl_xor_sync(0xffffffffu, totA, 2);
        winA += __shfl_xor_sync(0xffffffffu, winA, 1);
        winA += __shfl_xor_sync(0xffffffffu, winA, 2);
        totB += __shfl_xor_sync(0xffffffffu, totB, 1);
        totB += __shfl_xor_sync(0xffffffffu, totB, 2);
        winB += __shfl_xor_sync(0xffffffffu, winB, 1);
        winB += __shfl_xor_sync(0xffffffffu, winB, 2);

        float* red = (float*)sm;
        __syncthreads();
        if (tid == 0) red[0] = 0.f;
        __syncthreads();
        if (tg == 0) {
            float contrib = 0.f;
            if (rA < PF) contrib += winA / totA;
            if (rB < PF) contrib += winB / totB;
            if (contrib != 0.f) atomicAdd(red, contrib);
        }
        __syncthreads();
        if (tid == 0) atomicAdd(&ratio[type * NH + head], red[0] * (1.f / (float)PF));
        return;
    }

    // ================= attention path =================
    int tile, head, chunk = -1, eidx = 0;
    int lo0, hi0, lo1, hi1;
    if (blockIdx.x < 130) {
        tile = blockIdx.x >> 1; head = blockIdx.x & 1;
        lo0 = max(0, 2*tile - 32); hi0 = min(129, 2*tile + 33);
        lo1 = 130; hi1 = 150;
    } else {
        int e = blockIdx.x - 130;
        int tileIdx = e >> 4; head = (e >> 3) & 1; chunk = e & 7;
        tile = 65 + tileIdx;
        eidx = e;
        lo0 = chunk * 19; hi0 = min(150, chunk * 19 + 18);
        lo1 = 0; hi1 = -1;
    }
    const int r0 = tile * 128;
    const bool rowRazor = (tile < 65);
    const int n0 = hi0 - lo0 + 1;
    const int nb_total = n0 + (hi1 >= lo1 ? hi1 - lo1 + 1 : 0);

    const __half* qh = g_Qh + (size_t)head * S_TOT * HD;
    const __half* kh = g_Kh + (size_t)head * S_TOT * HD;
    const __half* kl = g_Kl + (size_t)head * S_TOT * HD;
    const __half* vh = g_Vh + (size_t)head * S_TOT * HD;

    // 3-stage prologue: issue loads for iters 0 and 1
    kv_load(sb + SKV0, lo0 * 64, tid, kh, kl, vh);
    CP_COMMIT();
    {
        const int b1 = (1 < n0) ? lo0 + 1 : lo1;
        kv_load(sb + SKV0 + KVBUF, b1 * 64, tid, kh, kl, vh);
        CP_COMMIT();
    }

#pragma unroll
    for (int it = 0; it < 8; it++) {
        int idx = tid + it * 256;
        int row = idx >> 4, ch = idx & 15;
        size_t src = (size_t)min(r0 + row, S_TOT - 1) * HD + ch * 8;
        *(uint4*)(sm + row * RSTR + ch * 16) = *(const uint4*)(qh + src);
    }

    const u32 aAddr = sb + (w * 16 + (lane & 15)) * RSTR + (lane >> 4) * 16;
    const u32 offBK = ((lane & 7) + ((lane >> 4) & 1) * 8) * RSTR + ((lane >> 3) & 1) * 16;
    const u32 offBV = 2*KROWS + ((lane & 7) + ((lane >> 3) & 1) * 8) * RSTR + ((lane >> 4) & 1) * 16;

    float o[16][4];
#pragma unroll
    for (int i = 0; i < 16; i++)
#pragma unroll
        for (int j = 0; j < 4; j++) o[i][j] = 0.f;
    float laccA = 0.f, laccB = 0.f;
    const int rA = r0 + w * 16 + g, rB = rA + 8;

    int stage = 0;
    for (int i = 0; i < nb_total; i++) {
        const int blk = (i < n0) ? lo0 + i : lo1 + (i - n0);
        const int c0 = blk * 64;
        int maskMode = 0;
        if (blk < 130) { if (rowRazor && (blk < 2*tile - 30 || blk > 2*tile + 31)) maskMode = 1; }
        else if (blk == 150) maskMode = 2;

        CP_WAIT1();            // current iter's group done (FIFO)
        __syncthreads();       // all warps past iter i-1 (its buffer now reusable)
        {
            int nxt = i + 2;
            if (nxt < nb_total) {
                const int nblk = (nxt < n0) ? lo0 + nxt : lo1 + (nxt - n0);
                int ns = stage + 2; if (ns >= 3) ns -= 3;
                kv_load(sb + SKV0 + ns * KVBUF, nblk * 64, tid, kh, kl, vh);
            }
            CP_COMMIT();       // always commit (possibly empty) to keep group count uniform
        }
        const u32 kvb = sb + SKV0 + stage * KVBUF;
        if (++stage == 3) stage = 0;

        // ---- QK: S = Qh*Kh + Qh*Kl (2-split) ----
        float s[8][4];
#pragma unroll
        for (int x = 0; x < 8; x++)
#pragma unroll
            for (int j = 0; j < 4; j++) s[x][j] = 0.f;

#pragma unroll
        for (int kc = 0; kc < 8; kc++) {
            u32 Ah[4];
            ldsm4(Ah, aAddr + kc * 32);
#pragma unroll
            for (int nb2 = 0; nb2 < 4; nb2++) {
                u32 Bh[4], Bl[4];
                u32 ba = kvb + offBK + nb2 * (16 * RSTR) + kc * 32;
                ldsm4(Bh, ba);
                ldsm4(Bl, ba + KROWS);
                mma(s[2*nb2],   Ah, Bh[0], Bh[1]);
                mma(s[2*nb2],   Ah, Bl[0], Bl[1]);
                mma(s[2*nb2+1], Ah, Bh[2], Bh[3]);
                mma(s[2*nb2+1], Ah, Bl[2], Bl[3]);
            }
        }

        // ---- epilogue: mask + exp + fp16 pack ----
        u32 ph[8][2];
#pragma unroll
        for (int nb = 0; nb < 8; nb++) {
            int c = c0 + nb * 8 + 2 * tg;
            float p00 = __expf(s[nb][0] * SCALE);
            float p01 = __expf(s[nb][1] * SCALE);
            float p10 = __expf(s[nb][2] * SCALE);
            float p11 = __expf(s[nb][3] * SCALE);
            if (maskMode == 1) {
                if ((unsigned)(c     - (rA - PRE)) > 2u*PRE) p00 = 0.f;
                if ((unsigned)(c + 1 - (rA - PRE)) > 2u*PRE) p01 = 0.f;
                if ((unsigned)(c     - (rB - PRE)) > 2u*PRE) p10 = 0.f;
                if ((unsigned)(c + 1 - (rB - PRE)) > 2u*PRE) p11 = 0.f;
            } else if (maskMode == 2) {
                if (c     >= S_TOT) { p00 = 0.f; p10 = 0.f; }
                if (c + 1 >= S_TOT) { p01 = 0.f; p11 = 0.f; }
            }
            laccA += p00 + p01;
            laccB += p10 + p11;
            ph[nb][0] = pack2(p00, p01);
            ph[nb][1] = pack2(p10, p11);
        }

        // ---- PV: O += P * Vh ----
#pragma unroll
        for (int kc = 0; kc < 4; kc++) {
            u32 Ah[4] = { ph[2*kc][0], ph[2*kc][1], ph[2*kc+1][0], ph[2*kc+1][1] };
#pragma unroll
            for (int nb2 = 0; nb2 < 8; nb2++) {
                u32 Bh[4];
                ldsm4t(Bh, kvb + offBV + kc * (16 * RSTR) + nb2 * 32);
                mma(o[2*nb2],   Ah, Bh[0], Bh[1]);
                mma(o[2*nb2+1], Ah, Bh[2], Bh[3]);
            }
        }
    }

    // ---- finalize ----
    laccA += __shfl_xor_sync(0xffffffffu, laccA, 1);
    laccA += __shfl_xor_sync(0xffffffffu, laccA, 2);
    laccB += __shfl_xor_sync(0xffffffffu, laccB, 1);
    laccB += __shfl_xor_sync(0xffffffffu, laccB, 2);

    if (chunk < 0) {
        float invA = 1.f / laccA, invB = 1.f / laccB;
        if (rA < S_TOT) {
            float* base = O + ((size_t)orig_idx(rA) * NH + head) * HD;
#pragma unroll
            for (int nb = 0; nb < 16; nb++)
                *(float2*)(base + nb * 8 + 2 * tg) = make_float2(o[nb][0] * invA, o[nb][1] * invA);
        }
        if (rB < S_TOT) {
            float* base = O + ((size_t)orig_idx(rB) * NH + head) * HD;
#pragma unroll
            for (int nb = 0; nb < 16; nb++)
                *(float2*)(base + nb * 8 + 2 * tg) = make_float2(o[nb][2] * invB, o[nb][3] * invB);
        }
    } else {
        float* so = g_scrO + (size_t)eidx * 16384;
        int rlA = w * 16 + g, rlB = rlA + 8;
#pragma unroll
        for (int nb = 0; nb < 16; nb++) {
            *(float2*)(so + rlA * 128 + nb * 8 + 2 * tg) = make_float2(o[nb][0], o[nb][1]);
            *(float2*)(so + rlB * 128 + nb * 8 + 2 * tg) = make_float2(o[nb][2], o[nb][3]);
        }
        if (tg == 0) {
            g_scrL[eidx * 128 + rlA] = laccA;
            g_scrL[eidx * 128 + rlB] = laccB;
        }
    }
}

// ---------------- combine tail partials (wide grid) ----------------
__global__ __launch_bounds__(256) void combine_kernel(float* __restrict__ O) {
    int pair  = blockIdx.x >> 4;
    int slice = blockIdx.x & 15;
    int tileIdx = pair >> 1, head = pair & 1;
    int tile = 65 + tileIdx, r0 = tile * 128;
    int ebase = tileIdx * 16 + head * 8;
    int tid = threadIdx.x;

    __shared__ float ls[8];
    if (tid < 8) {
        int row = slice * 8 + tid;
        float sum = 0.f;
#pragma unroll
        for (int c = 0; c < NCHUNK; c++) sum += g_scrL[(ebase + c) * 128 + row];
        ls[tid] = 1.f / sum;
    }
    __syncthreads();

#pragma unroll
    for (int r = 0; r < 4; r++) {
        int k = slice * 1024 + r * 256 + tid;
        int row = k >> 7, col = k & 127;
        if (r0 + row >= S_TOT) continue;
        float sum = 0.f;
#pragma unroll
        for (int c = 0; c < NCHUNK; c++) sum += g_scrO[(size_t)(ebase + c) * 16384 + k];
        int gr = orig_idx(r0 + row);
        O[((size_t)gr * NH + head) * HD + col] = sum * ls[row - slice * 8];
    }
}

__global__ void zero_ratio(float* r) {
    if (threadIdx.x < 4) r[threadIdx.x] = 0.f;
}

// ---------------- launch ----------------
extern "C" void kernel_launch(void* const* d_in, const int* in_sizes, int n_in,
                              void* d_out, int out_size)
{
    const float* Q = (const float*)d_in[0];
    const float* K = (const float*)d_in[1];
    const float* V = (const float*)d_in[2];
    float* O     = (float*)d_out;
    float* ratio = O + (size_t)S_TOT * NH * HD;

    cudaFuncSetAttribute(fused_kernel, cudaFuncAttributeMaxDynamicSharedMemorySize, SMEM_ATTN);

    zero_ratio<<<1, 32>>>(ratio);
    prep_qkv<<<dim3(1202, NH), 256>>>(Q, K, V);
    fused_kernel<<<342, 256, SMEM_ATTN>>>(O, ratio);
    combine_kernel<<<352, 256>>>(O);
}

// round 10
// speedup vs baseline: 14.3094x; 1.5070x over previous
#include <cuda_runtime.h>
#include <cuda_fp16.h>
#include <math.h>

typedef unsigned int u32;

// ---------------- problem constants ----------------
#define S_TOT 9616
#define RAZOR 8320
#define PF    1040
#define ROT   8576
#define NH    2
#define HD    128
#define PRE   2048
#define WIN   301
// SCALE * log2(e), absorbed into Q at prep; scores exponentiated with ex2
#define QSCALE 0.12751741522f

// rotated fp16 buffers [h][s][d]  (Q pre-scaled by QSCALE)
__device__ __half g_Qh[(size_t)NH*S_TOT*HD];
__device__ __half g_Kh[(size_t)NH*S_TOT*HD];
__device__ __half g_Vh[(size_t)NH*S_TOT*HD];

// tail-tile partial scratch: 11 tiles x 2 heads x 8 chunks
#define NCHUNK 8
__device__ float g_scrO[(size_t)11*2*NCHUNK*128*128];
__device__ float g_scrL[(size_t)11*2*NCHUNK*128];

__device__ __forceinline__ int orig_idx(int r) { return r < ROT ? r + PF : r - ROT; }

__device__ __forceinline__ u32 smem_u32(const void* p) {
    u32 a;
    asm("{ .reg .u64 t; cvta.to.shared.u64 t, %1; cvt.u32.u64 %0, t; }" : "=r"(a) : "l"(p));
    return a;
}
__device__ __forceinline__ void ldsm4(u32* r, u32 a) {
    asm volatile("ldmatrix.sync.aligned.m8n8.x4.shared.b16 {%0,%1,%2,%3}, [%4];"
                 : "=r"(r[0]), "=r"(r[1]), "=r"(r[2]), "=r"(r[3]) : "r"(a));
}
__device__ __forceinline__ void ldsm4t(u32* r, u32 a) {
    asm volatile("ldmatrix.sync.aligned.m8n8.x4.trans.shared.b16 {%0,%1,%2,%3}, [%4];"
                 : "=r"(r[0]), "=r"(r[1]), "=r"(r[2]), "=r"(r[3]) : "r"(a));
}
__device__ __forceinline__ void mma(float* d, const u32* a, u32 b0, u32 b1) {
    asm volatile("mma.sync.aligned.m16n8k16.row.col.f32.f16.f16.f32 "
                 "{%0,%1,%2,%3},{%4,%5,%6,%7},{%8,%9},{%0,%1,%2,%3};"
                 : "+f"(d[0]), "+f"(d[1]), "+f"(d[2]), "+f"(d[3])
                 : "r"(a[0]), "r"(a[1]), "r"(a[2]), "r"(a[3]), "r"(b0), "r"(b1));
}
__device__ __forceinline__ u32 pack2(float a, float b) {
    __half2 t = __floats2half2_rn(a, b);
    return *(u32*)&t;
}
__device__ __forceinline__ float ex2(float x) {
    float r;
    asm("ex2.approx.ftz.f32 %0, %1;" : "=f"(r) : "f"(x));
    return r;
}

#define CP_ASYNC16(d, s) asm volatile("cp.async.cg.shared.global [%0], [%1], 16;" :: "r"(d), "l"(s))
#define CP_COMMIT()      asm volatile("cp.async.commit_group;" ::: "memory")
#define CP_WAIT2()       asm volatile("cp.async.wait_group 2;" ::: "memory")

// ---------------- smem layout ----------------
#define RSTR 272
#define QTILE (128*RSTR)               // 34816 (Qh)
#define KROWS (64*RSTR)                // 17408
#define KVBUF (2*KROWS)                // 34816: [KH|VH]
#define SKV0  QTILE
#define NSTG  4
#define SMEM_ATTN (SKV0 + NSTG*KVBUF)  // 174080

// ---------------- prep: rotate + fp16 convert (Q pre-scaled) ----------------
__global__ __launch_bounds__(256) void prep_qkv(const float* __restrict__ Q,
                                                const float* __restrict__ K,
                                                const float* __restrict__ V) {
    int h = blockIdx.y;
    int s = blockIdx.x * 8 + (threadIdx.x >> 5);
    if (s >= S_TOT) return;
    int lane = threadIdx.x & 31;
    int gq = orig_idx(s);
    size_t si = ((size_t)gq * NH + h) * HD + lane * 4;
    size_t o  = ((size_t)h * S_TOT + s) * HD + lane * 4;
    float4 qv = *(const float4*)(Q + si);
    float4 kv = *(const float4*)(K + si);
    float4 vv = *(const float4*)(V + si);
    *(uint2*)(g_Qh + o) = make_uint2(pack2(qv.x * QSCALE, qv.y * QSCALE),
                                     pack2(qv.z * QSCALE, qv.w * QSCALE));
    *(uint2*)(g_Kh + o) = make_uint2(pack2(kv.x, kv.y), pack2(kv.z, kv.w));
    *(uint2*)(g_Vh + o) = make_uint2(pack2(vv.x, vv.y), pack2(vv.z, vv.w));
}

// ---------------- async KV block load (Kh, Vh) ----------------
__device__ __forceinline__ void kv_load(u32 kvb, int c0, int tid,
    const __half* kh, const __half* vh)
{
#pragma unroll
    for (int it = 0; it < 4; it++) {
        int idx = tid + it * 256;
        int row = idx >> 4, ch = idx & 15;
        size_t src = (size_t)min(c0 + row, S_TOT - 1) * HD + ch * 8;
        u32 dst = kvb + row * RSTR + ch * 16;
        CP_ASYNC16(dst,         kh + src);
        CP_ASYNC16(dst + KROWS, vh + src);
    }
}

// ---------------- fused attention + ratio kernel ----------------
__global__ __launch_bounds__(256, 1)
void fused_kernel(float* __restrict__ O, float* __restrict__ ratio)
{
    extern __shared__ char sm[];
    const u32 sb  = smem_u32(sm);
    const int tid = threadIdx.x, w = tid >> 5, lane = tid & 31;
    const int g = lane >> 2, tg = lane & 3;

    if (blockIdx.x >= 306) {
        // ================= ratio path (fp16 QK) =================
        int e = blockIdx.x - 306;            // 0..35
        const int type = e / 18, head = (e / 9) & 1, rb = e % 9;
        const int r0 = rb * 128;
        const int stride = type ? 8 : 1;

        const __half* qh = g_Qh + (size_t)head * S_TOT * HD;
        const __half* kh = g_Kh + (size_t)head * S_TOT * HD;

#pragma unroll
        for (int it = 0; it < 8; it++) {
            int idx = tid + it * 256;
            int row = idx >> 4, ch = idx & 15;
            size_t src = (size_t)(min(r0 + row, PF - 1) * stride) * HD + ch * 8;
            *(uint4*)(sm + row * RSTR + ch * 16) = *(const uint4*)(qh + src);
        }

        const u32 aAddr = sb + (w * 16 + (lane & 15)) * RSTR + (lane >> 4) * 16;
        const u32 bAddr = sb + QTILE + ((lane & 7) + ((lane >> 4) & 1) * 8) * RSTR
                        + ((lane >> 3) & 1) * 16;

        float totA = 0.f, winA = 0.f, totB = 0.f, winB = 0.f;
        const int rA = r0 + w * 16 + g, rB = rA + 8;

        for (int blk = 0; blk < 17; blk++) {
            const int c0 = blk * 64;
            __syncthreads();
#pragma unroll
            for (int it = 0; it < 4; it++) {
                int idx = tid + it * 256;
                int row = idx >> 4, ch = idx & 15;
                size_t src = (size_t)(min(c0 + row, PF - 1) * stride) * HD + ch * 8;
                *(uint4*)(sm + QTILE + row * RSTR + ch * 16) = *(const uint4*)(kh + src);
            }
            __syncthreads();

            float s[8][4];
#pragma unroll
            for (int x = 0; x < 8; x++)
#pragma unroll
                for (int j = 0; j < 4; j++) s[x][j] = 0.f;
#pragma unroll
            for (int kc = 0; kc < 8; kc++) {
                u32 Ah[4];
                ldsm4(Ah, aAddr + kc * 32);
#pragma unroll
                for (int nb2 = 0; nb2 < 4; nb2++) {
                    u32 Bh[4];
                    ldsm4(Bh, bAddr + nb2 * (16 * RSTR) + kc * 32);
                    mma(s[2*nb2],   Ah, Bh[0], Bh[1]);
                    mma(s[2*nb2+1], Ah, Bh[2], Bh[3]);
                }
            }
#pragma unroll
            for (int nb = 0; nb < 8; nb++) {
                int c = c0 + nb * 8 + 2 * tg;
#pragma unroll
                for (int v = 0; v < 4; v++) {
                    int cc = c + (v & 1);
                    int rr = (v < 2) ? rA : rB;
                    float p = (cc < PF) ? ex2(s[nb][v]) : 0.f;
                    if (v < 2) { totA += p; if (abs(rr - cc) <= WIN) winA += p; }
                    else       { totB += p; if (abs(rr - cc) <= WIN) winB += p; }
                }
            }
        }

        totA += __shfl_xor_sync(0xffffffffu, totA, 1);
        totA += __shfl_xor_sync(0xffffffffu, totA, 2);
        winA += __shfl_xor_sync(0xffffffffu, winA, 1);
        winA += __shfl_xor_sync(0xffffffffu, winA, 2);
        totB += __shfl_xor_sync(0xffffffffu, totB, 1);
        totB += __shfl_xor_sync(0xffffffffu, totB, 2);
        winB += __shfl_xor_sync(0xffffffffu, winB, 1);
        winB += __shfl_xor_sync(0xffffffffu, winB, 2);

        float* red = (float*)sm;
        __syncthreads();
        if (tid == 0) red[0] = 0.f;
        __syncthreads();
        if (tg == 0) {
            float contrib = 0.f;
            if (rA < PF) contrib += winA / totA;
            if (rB < PF) contrib += winB / totB;
            if (contrib != 0.f) atomicAdd(red, contrib);
        }
        __syncthreads();
        if (tid == 0) atomicAdd(&ratio[type * NH + head], red[0] * (1.f / (float)PF));
        return;
    }

    // ================= attention path =================
    int tile, head, chunk = -1, eidx = 0;
    int lo0, hi0, lo1, hi1;
    if (blockIdx.x < 130) {
        tile = blockIdx.x >> 1; head = blockIdx.x & 1;
        lo0 = max(0, 2*tile - 32); hi0 = min(129, 2*tile + 33);
        lo1 = 130; hi1 = 150;
    } else {
        int e = blockIdx.x - 130;
        int tileIdx = e >> 4; head = (e >> 3) & 1; chunk = e & 7;
        tile = 65 + tileIdx;
        eidx = e;
        lo0 = chunk * 19; hi0 = min(150, chunk * 19 + 18);
        lo1 = 0; hi1 = -1;
    }
    const int r0 = tile * 128;
    const bool rowRazor = (tile < 65);
    const int n0 = hi0 - lo0 + 1;
    const int nb_total = n0 + (hi1 >= lo1 ? hi1 - lo1 + 1 : 0);

    const __half* qh = g_Qh + (size_t)head * S_TOT * HD;
    const __half* kh = g_Kh + (size_t)head * S_TOT * HD;
    const __half* vh = g_Vh + (size_t)head * S_TOT * HD;

    // block index helper (flattened two segments)
#define BLK_OF(j) (((j) < n0) ? lo0 + (j) : lo1 + ((j) - n0))

    // prologue: issue loads for iters 0,1,2
#pragma unroll
    for (int j = 0; j < 3; j++) {
        int jj = min(j, nb_total - 1);
        kv_load(sb + SKV0 + j * KVBUF, BLK_OF(jj) * 64, tid, kh, vh);
        CP_COMMIT();
    }

#pragma unroll
    for (int it = 0; it < 8; it++) {
        int idx = tid + it * 256;
        int row = idx >> 4, ch = idx & 15;
        size_t src = (size_t)min(r0 + row, S_TOT - 1) * HD + ch * 8;
        *(uint4*)(sm + row * RSTR + ch * 16) = *(const uint4*)(qh + src);
    }

    const u32 aAddr = sb + (w * 16 + (lane & 15)) * RSTR + (lane >> 4) * 16;
    const u32 offBK = ((lane & 7) + ((lane >> 4) & 1) * 8) * RSTR + ((lane >> 3) & 1) * 16;
    const u32 offBV = KROWS + ((lane & 7) + ((lane >> 3) & 1) * 8) * RSTR + ((lane >> 4) & 1) * 16;

    float o[16][4];
#pragma unroll
    for (int i = 0; i < 16; i++)
#pragma unroll
        for (int j = 0; j < 4; j++) o[i][j] = 0.f;
    float laccA = 0.f, laccB = 0.f;
    const int rA = r0 + w * 16 + g, rB = rA + 8;

    int stage = 0;
    for (int i = 0; i < nb_total; i++) {
        const int blk = BLK_OF(i);
        const int c0 = blk * 64;
        int maskMode = 0;
        if (blk < 130) { if (rowRazor && (blk < 2*tile - 30 || blk > 2*tile + 31)) maskMode = 1; }
        else if (blk == 150) maskMode = 2;

        CP_WAIT2();            // iter i's group done (FIFO, <=2 outstanding)
        __syncthreads();       // copies visible CTA-wide; all warps past iter i-1
        {
            int nxt = i + 3;
            if (nxt < nb_total) {
                int ns = stage + 3; if (ns >= NSTG) ns -= NSTG;
                kv_load(sb + SKV0 + ns * KVBUF, BLK_OF(nxt) * 64, tid, kh, vh);
            }
            CP_COMMIT();       // uniform group counting
        }
        const u32 kvb = sb + SKV0 + stage * KVBUF;
        if (++stage == NSTG) stage = 0;

        // ---- QK: S = Qh * Kh (fp16) ----
        float s[8][4];
#pragma unroll
        for (int x = 0; x < 8; x++)
#pragma unroll
            for (int j = 0; j < 4; j++) s[x][j] = 0.f;

#pragma unroll
        for (int kc = 0; kc < 8; kc++) {
            u32 Ah[4];
            ldsm4(Ah, aAddr + kc * 32);
#pragma unroll
            for (int nb2 = 0; nb2 < 4; nb2++) {
                u32 Bh[4];
                ldsm4(Bh, kvb + offBK + nb2 * (16 * RSTR) + kc * 32);
                mma(s[2*nb2],   Ah, Bh[0], Bh[1]);
                mma(s[2*nb2+1], Ah, Bh[2], Bh[3]);
            }
        }

        // ---- epilogue: mask + ex2 + fp16 pack ----
        u32 ph[8][2];
#pragma unroll
        for (int nb = 0; nb < 8; nb++) {
            int c = c0 + nb * 8 + 2 * tg;
            float p00 = ex2(s[nb][0]);
            float p01 = ex2(s[nb][1]);
            float p10 = ex2(s[nb][2]);
            float p11 = ex2(s[nb][3]);
            if (maskMode == 1) {
                if ((unsigned)(c     - (rA - PRE)) > 2u*PRE) p00 = 0.f;
                if ((unsigned)(c + 1 - (rA - PRE)) > 2u*PRE) p01 = 0.f;
                if ((unsigned)(c     - (rB - PRE)) > 2u*PRE) p10 = 0.f;
                if ((unsigned)(c + 1 - (rB - PRE)) > 2u*PRE) p11 = 0.f;
            } else if (maskMode == 2) {
                if (c     >= S_TOT) { p00 = 0.f; p10 = 0.f; }
                if (c + 1 >= S_TOT) { p01 = 0.f; p11 = 0.f; }
            }
            laccA += p00 + p01;
            laccB += p10 + p11;
            ph[nb][0] = pack2(p00, p01);
            ph[nb][1] = pack2(p10, p11);
        }

        // ---- PV: O += P * Vh ----
#pragma unroll
        for (int kc = 0; kc < 4; kc++) {
            u32 Ah[4] = { ph[2*kc][0], ph[2*kc][1], ph[2*kc+1][0], ph[2*kc+1][1] };
#pragma unroll
            for (int nb2 = 0; nb2 < 8; nb2++) {
                u32 Bh[4];
                ldsm4t(Bh, kvb + offBV + kc * (16 * RSTR) + nb2 * 32);
                mma(o[2*nb2],   Ah, Bh[0], Bh[1]);
                mma(o[2*nb2+1], Ah, Bh[2], Bh[3]);
            }
        }
    }

    // ---- finalize ----
    laccA += __shfl_xor_sync(0xffffffffu, laccA, 1);
    laccA += __shfl_xor_sync(0xffffffffu, laccA, 2);
    laccB += __shfl_xor_sync(0xffffffffu, laccB, 1);
    laccB += __shfl_xor_sync(0xffffffffu, laccB, 2);

    if (chunk < 0) {
        float invA = 1.f / laccA, invB = 1.f / laccB;
        if (rA < S_TOT) {
            float* base = O + ((size_t)orig_idx(rA) * NH + head) * HD;
#pragma unroll
            for (int nb = 0; nb < 16; nb++)
                *(float2*)(base + nb * 8 + 2 * tg) = make_float2(o[nb][0] * invA, o[nb][1] * invA);
        }
        if (rB < S_TOT) {
            float* base = O + ((size_t)orig_idx(rB) * NH + head) * HD;
#pragma unroll
            for (int nb = 0; nb < 16; nb++)
                *(float2*)(base + nb * 8 + 2 * tg) = make_float2(o[nb][2] * invB, o[nb][3] * invB);
        }
    } else {
        float* so = g_scrO + (size_t)eidx * 16384;
        int rlA = w * 16 + g, rlB = rlA + 8;
#pragma unroll
        for (int nb = 0; nb < 16; nb++) {
            *(float2*)(so + rlA * 128 + nb * 8 + 2 * tg) = make_float2(o[nb][0], o[nb][1]);
            *(float2*)(so + rlB * 128 + nb * 8 + 2 * tg) = make_float2(o[nb][2], o[nb][3]);
        }
        if (tg == 0) {
            g_scrL[eidx * 128 + rlA] = laccA;
            g_scrL[eidx * 128 + rlB] = laccB;
        }
    }
}

// ---------------- combine tail partials (wide grid) ----------------
__global__ __launch_bounds__(256) void combine_kernel(float* __restrict__ O) {
    int pair  = blockIdx.x >> 4;
    int slice = blockIdx.x & 15;
    int tileIdx = pair >> 1, head = pair & 1;
    int tile = 65 + tileIdx, r0 = tile * 128;
    int ebase = tileIdx * 16 + head * 8;
    int tid = threadIdx.x;

    __shared__ float ls[8];
    if (tid < 8) {
        int row = slice * 8 + tid;
        float sum = 0.f;
#pragma unroll
        for (int c = 0; c < NCHUNK; c++) sum += g_scrL[(ebase + c) * 128 + row];
        ls[tid] = 1.f / sum;
    }
    __syncthreads();

#pragma unroll
    for (int r = 0; r < 4; r++) {
        int k = slice * 1024 + r * 256 + tid;
        int row = k >> 7, col = k & 127;
        if (r0 + row >= S_TOT) continue;
        float sum = 0.f;
#pragma unroll
        for (int c = 0; c < NCHUNK; c++) sum += g_scrO[(size_t)(ebase + c) * 16384 + k];
        int gr = orig_idx(r0 + row);
        O[((size_t)gr * NH + head) * HD + col] = sum * ls[row - slice * 8];
    }
}

__global__ void zero_ratio(float* r) {
    if (threadIdx.x < 4) r[threadIdx.x] = 0.f;
}

// ---------------- launch ----------------
extern "C" void kernel_launch(void* const* d_in, const int* in_sizes, int n_in,
                              void* d_out, int out_size)
{
    const float* Q = (const float*)d_in[0];
    const float* K = (const float*)d_in[1];
    const float* V = (const float*)d_in[2];
    float* O     = (float*)d_out;
    float* ratio = O + (size_t)S_TOT * NH * HD;

    cudaFuncSetAttribute(fused_kernel, cudaFuncAttributeMaxDynamicSharedMemorySize, SMEM_ATTN);

    zero_ratio<<<1, 32>>>(ratio);
    prep_qkv<<<dim3(1202, NH), 256>>>(Q, K, V);
    fused_kernel<<<342, 256, SMEM_ATTN>>>(O, ratio);
    combine_kernel<<<352, 256>>>(O);
}

// round 11
// speedup vs baseline: 15.2757x; 1.0675x over previous
#include <cuda_runtime.h>
#include <cuda_fp16.h>
#include <math.h>

typedef unsigned int u32;

// ---------------- problem constants ----------------
#define S_TOT 9616
#define RAZOR 8320
#define PF    1040
#define ROT   8576
#define NH    2
#define HD    128
#define PRE   2048
#define WIN   301
// SCALE * log2(e), absorbed into Q at prep; scores exponentiated with ex2
#define QSCALE 0.12751741522f
#define ONES16 0x3C003C00u     // fp16 {1.0, 1.0}

// rotated fp16 buffers [h][s][d]  (Q pre-scaled by QSCALE)
__device__ __half g_Qh[(size_t)NH*S_TOT*HD];
__device__ __half g_Kh[(size_t)NH*S_TOT*HD];
__device__ __half g_Vh[(size_t)NH*S_TOT*HD];

// tail-tile partial scratch: 11 tiles x 2 heads x 8 chunks
#define NCHUNK 8
__device__ float g_scrO[(size_t)11*2*NCHUNK*128*128];
__device__ float g_scrL[(size_t)11*2*NCHUNK*128];

__device__ __forceinline__ int orig_idx(int r) { return r < ROT ? r + PF : r - ROT; }

__device__ __forceinline__ u32 smem_u32(const void* p) {
    u32 a;
    asm("{ .reg .u64 t; cvta.to.shared.u64 t, %1; cvt.u32.u64 %0, t; }" : "=r"(a) : "l"(p));
    return a;
}
__device__ __forceinline__ void ldsm4(u32* r, u32 a) {
    asm volatile("ldmatrix.sync.aligned.m8n8.x4.shared.b16 {%0,%1,%2,%3}, [%4];"
                 : "=r"(r[0]), "=r"(r[1]), "=r"(r[2]), "=r"(r[3]) : "r"(a));
}
__device__ __forceinline__ void ldsm4t(u32* r, u32 a) {
    asm volatile("ldmatrix.sync.aligned.m8n8.x4.trans.shared.b16 {%0,%1,%2,%3}, [%4];"
                 : "=r"(r[0]), "=r"(r[1]), "=r"(r[2]), "=r"(r[3]) : "r"(a));
}
__device__ __forceinline__ void mma(float* d, const u32* a, u32 b0, u32 b1) {
    asm volatile("mma.sync.aligned.m16n8k16.row.col.f32.f16.f16.f32 "
                 "{%0,%1,%2,%3},{%4,%5,%6,%7},{%8,%9},{%0,%1,%2,%3};"
                 : "+f"(d[0]), "+f"(d[1]), "+f"(d[2]), "+f"(d[3])
                 : "r"(a[0]), "r"(a[1]), "r"(a[2]), "r"(a[3]), "r"(b0), "r"(b1));
}
__device__ __forceinline__ u32 pack2(float a, float b) {
    __half2 t = __floats2half2_rn(a, b);
    return *(u32*)&t;
}
__device__ __forceinline__ float ex2(float x) {
    float r;
    asm("ex2.approx.ftz.f32 %0, %1;" : "=f"(r) : "f"(x));
    return r;
}

#define CP_ASYNC16(d, s) asm volatile("cp.async.cg.shared.global [%0], [%1], 16;" :: "r"(d), "l"(s))
#define CP_COMMIT()      asm volatile("cp.async.commit_group;" ::: "memory")
#define CP_WAIT0()       asm volatile("cp.async.wait_group 0;" ::: "memory")

// ---------------- smem layout ----------------
#define RSTR 272
#define QTILE (128*RSTR)               // 34816 (Qh)
#define KROWS (128*RSTR)               // 34816: 128 K rows per buffer
#define KVBUF (2*KROWS)                // 69632: [KH(128r) | VH(128r)]
#define SKV0  QTILE
#define SMEM_ATTN (SKV0 + 2*KVBUF)     // 174080

// ---------------- prep: rotate + fp16 convert (Q pre-scaled) + zero ratio ----------------
__global__ __launch_bounds__(256) void prep_qkv(const float* __restrict__ Q,
                                                const float* __restrict__ K,
                                                const float* __restrict__ V,
                                                float* __restrict__ ratio) {
    if (blockIdx.x == 0 && blockIdx.y == 0 && threadIdx.x < 4) ratio[threadIdx.x] = 0.f;
    int h = blockIdx.y;
    int s = blockIdx.x * 8 + (threadIdx.x >> 5);
    if (s >= S_TOT) return;
    int lane = threadIdx.x & 31;
    int gq = orig_idx(s);
    size_t si = ((size_t)gq * NH + h) * HD + lane * 4;
    size_t o  = ((size_t)h * S_TOT + s) * HD + lane * 4;
    float4 qv = *(const float4*)(Q + si);
    float4 kv = *(const float4*)(K + si);
    float4 vv = *(const float4*)(V + si);
    *(uint2*)(g_Qh + o) = make_uint2(pack2(qv.x * QSCALE, qv.y * QSCALE),
                                     pack2(qv.z * QSCALE, qv.w * QSCALE));
    *(uint2*)(g_Kh + o) = make_uint2(pack2(kv.x, kv.y), pack2(kv.z, kv.w));
    *(uint2*)(g_Vh + o) = make_uint2(pack2(vv.x, vv.y), pack2(vv.z, vv.w));
}

// ---------------- async KV block load: 128 rows of K and V ----------------
__device__ __forceinline__ void kv_load(u32 kvb, int c0, int tid,
    const __half* kh, const __half* vh)
{
#pragma unroll
    for (int it = 0; it < 8; it++) {
        int idx = tid + it * 256;            // 0..2047
        int row = idx >> 4, ch = idx & 15;
        size_t src = (size_t)min(c0 + row, S_TOT - 1) * HD + ch * 8;
        u32 dst = kvb + row * RSTR + ch * 16;
        CP_ASYNC16(dst,         kh + src);
        CP_ASYNC16(dst + KROWS, vh + src);
    }
}

// ---------------- fused attention + ratio kernel ----------------
__global__ __launch_bounds__(256, 1)
void fused_kernel(float* __restrict__ O, float* __restrict__ ratio)
{
    extern __shared__ char sm[];
    const u32 sb  = smem_u32(sm);
    const int tid = threadIdx.x, w = tid >> 5, lane = tid & 31;
    const int g = lane >> 2, tg = lane & 3;

    if (blockIdx.x >= 306) {
        // ================= ratio path (fp16 QK, 64-col blocks) =================
        int e = blockIdx.x - 306;            // 0..35
        const int type = e / 18, head = (e / 9) & 1, rb = e % 9;
        const int r0 = rb * 128;
        const int stride = type ? 8 : 1;

        const __half* qh = g_Qh + (size_t)head * S_TOT * HD;
        const __half* kh = g_Kh + (size_t)head * S_TOT * HD;

#pragma unroll
        for (int it = 0; it < 8; it++) {
            int idx = tid + it * 256;
            int row = idx >> 4, ch = idx & 15;
            size_t src = (size_t)(min(r0 + row, PF - 1) * stride) * HD + ch * 8;
            *(uint4*)(sm + row * RSTR + ch * 16) = *(const uint4*)(qh + src);
        }

        const u32 aAddr = sb + (w * 16 + (lane & 15)) * RSTR + (lane >> 4) * 16;
        const u32 bAddr = sb + QTILE + ((lane & 7) + ((lane >> 4) & 1) * 8) * RSTR
                        + ((lane >> 3) & 1) * 16;

        float totA = 0.f, winA = 0.f, totB = 0.f, winB = 0.f;
        const int rA = r0 + w * 16 + g, rB = rA + 8;

        for (int blk = 0; blk < 17; blk++) {
            const int c0 = blk * 64;
            __syncthreads();
#pragma unroll
            for (int it = 0; it < 4; it++) {
                int idx = tid + it * 256;
                int row = idx >> 4, ch = idx & 15;
                size_t src = (size_t)(min(c0 + row, PF - 1) * stride) * HD + ch * 8;
                *(uint4*)(sm + QTILE + row * RSTR + ch * 16) = *(const uint4*)(kh + src);
            }
            __syncthreads();

            float s[8][4];
#pragma unroll
            for (int x = 0; x < 8; x++)
#pragma unroll
                for (int j = 0; j < 4; j++) s[x][j] = 0.f;
#pragma unroll
            for (int kc = 0; kc < 8; kc++) {
                u32 Ah[4];
                ldsm4(Ah, aAddr + kc * 32);
#pragma unroll
                for (int nb2 = 0; nb2 < 4; nb2++) {
                    u32 Bh[4];
                    ldsm4(Bh, bAddr + nb2 * (16 * RSTR) + kc * 32);
                    mma(s[2*nb2],   Ah, Bh[0], Bh[1]);
                    mma(s[2*nb2+1], Ah, Bh[2], Bh[3]);
                }
            }
#pragma unroll
            for (int nb = 0; nb < 8; nb++) {
                int c = c0 + nb * 8 + 2 * tg;
#pragma unroll
                for (int v = 0; v < 4; v++) {
                    int cc = c + (v & 1);
                    int rr = (v < 2) ? rA : rB;
                    float p = (cc < PF) ? ex2(s[nb][v]) : 0.f;
                    if (v < 2) { totA += p; if (abs(rr - cc) <= WIN) winA += p; }
                    else       { totB += p; if (abs(rr - cc) <= WIN) winB += p; }
                }
            }
        }

        totA += __shfl_xor_sync(0xffffffffu, totA, 1);
        totA += __shfl_xor_sync(0xffffffffu, totA, 2);
        winA += __shfl_xor_sync(0xffffffffu, winA, 1);
        winA += __shfl_xor_sync(0xffffffffu, winA, 2);
        totB += __shfl_xor_sync(0xffffffffu, totB, 1);
        totB += __shfl_xor_sync(0xffffffffu, totB, 2);
        winB += __shfl_xor_sync(0xffffffffu, winB, 1);
        winB += __shfl_xor_sync(0xffffffffu, winB, 2);

        float* red = (float*)sm;
        __syncthreads();
        if (tid == 0) red[0] = 0.f;
        __syncthreads();
        if (tg == 0) {
            float contrib = 0.f;
            if (rA < PF) contrib += winA / totA;
            if (rB < PF) contrib += winB / totB;
            if (contrib != 0.f) atomicAdd(red, contrib);
        }
        __syncthreads();
        if (tid == 0) atomicAdd(&ratio[type * NH + head], red[0] * (1.f / (float)PF));
        return;
    }

    // ================= attention path (128-col big-iters, two 64-col halves) =================
    int tile, head, chunk = -1, eidx = 0;
    int lo0, hi0, lo1, hi1;
    if (blockIdx.x < 130) {
        tile = blockIdx.x >> 1; head = blockIdx.x & 1;
        lo0 = max(0, tile - 16); hi0 = min(64, tile + 16);   // band, 128-blocks
        lo1 = 65; hi1 = 75;                                   // tail
    } else {
        int e = blockIdx.x - 130;
        int tileIdx = e >> 4; head = (e >> 3) & 1; chunk = e & 7;
        tile = 65 + tileIdx;
        eidx = e;
        lo0 = (76 * chunk) / 8; hi0 = (76 * (chunk + 1)) / 8 - 1;
        lo1 = 0; hi1 = -1;
    }
    const int r0 = tile * 128;
    const bool rowRazor = (tile < 65);
    const int n0 = hi0 - lo0 + 1;
    const int nb_total = n0 + (hi1 >= lo1 ? hi1 - lo1 + 1 : 0);

    const __half* qh = g_Qh + (size_t)head * S_TOT * HD;
    const __half* kh = g_Kh + (size_t)head * S_TOT * HD;
    const __half* vh = g_Vh + (size_t)head * S_TOT * HD;

#define BLK_OF(j) (((j) < n0) ? lo0 + (j) : lo1 + ((j) - n0))

    // prologue: issue load for big-iter 0
    kv_load(sb + SKV0, BLK_OF(0) * 128, tid, kh, vh);
    CP_COMMIT();

#pragma unroll
    for (int it = 0; it < 8; it++) {
        int idx = tid + it * 256;
        int row = idx >> 4, ch = idx & 15;
        size_t src = (size_t)min(r0 + row, S_TOT - 1) * HD + ch * 8;
        *(uint4*)(sm + row * RSTR + ch * 16) = *(const uint4*)(qh + src);
    }

    const u32 aAddr = sb + (w * 16 + (lane & 15)) * RSTR + (lane >> 4) * 16;
    const u32 offBK = ((lane & 7) + ((lane >> 4) & 1) * 8) * RSTR + ((lane >> 3) & 1) * 16;
    const u32 offBV = KROWS + ((lane & 7) + ((lane >> 3) & 1) * 8) * RSTR + ((lane >> 4) & 1) * 16;

    float o[16][4];
#pragma unroll
    for (int i = 0; i < 16; i++)
#pragma unroll
        for (int j = 0; j < 4; j++) o[i][j] = 0.f;
    float laccF[4] = {0.f, 0.f, 0.f, 0.f};      // row sums via ones-MMA
    const int rA = r0 + w * 16 + g, rB = rA + 8;
    const int t2lo = 2 * tile - 30, t2hi = 2 * tile + 31;

    for (int i = 0; i < nb_total; i++) {
        const int blk = BLK_OF(i);

        CP_WAIT0();            // this iter's KV resident
        __syncthreads();       // all warps done with the other buffer
        {
            int nxt = i + 1;
            if (nxt < nb_total)
                kv_load(sb + SKV0 + (nxt & 1) * KVBUF, BLK_OF(nxt) * 128, tid, kh, vh);
            CP_COMMIT();       // uniform group counting
        }
        const u32 kvb = sb + SKV0 + (i & 1) * KVBUF;

#pragma unroll
        for (int h = 0; h < 2; h++) {
            const int sub = 2 * blk + h;          // 64-col sub-block index
            if (sub == 151) continue;             // beyond sequence entirely
            const int c0 = sub * 64;
            int maskMode = 0;
            if (sub < 130) { if (rowRazor && (sub < t2lo || sub > t2hi)) maskMode = 1; }
            else if (sub == 150) maskMode = 2;
            const u32 hof = h * (64 * RSTR);

            // ---- QK: S = Qh * Kh ----
            float s[8][4];
#pragma unroll
            for (int x = 0; x < 8; x++)
#pragma unroll
                for (int j = 0; j < 4; j++) s[x][j] = 0.f;

#pragma unroll
            for (int kc = 0; kc < 8; kc++) {
                u32 Ah[4];
                ldsm4(Ah, aAddr + kc * 32);
#pragma unroll
                for (int nb2 = 0; nb2 < 4; nb2++) {
                    u32 Bh[4];
                    ldsm4(Bh, kvb + offBK + hof + nb2 * (16 * RSTR) + kc * 32);
                    mma(s[2*nb2],   Ah, Bh[0], Bh[1]);
                    mma(s[2*nb2+1], Ah, Bh[2], Bh[3]);
                }
            }

            // ---- epilogue: mask + ex2 + fp16 pack ----
            u32 ph[8][2];
#pragma unroll
            for (int nb = 0; nb < 8; nb++) {
                int c = c0 + nb * 8 + 2 * tg;
                float p00 = ex2(s[nb][0]);
                float p01 = ex2(s[nb][1]);
                float p10 = ex2(s[nb][2]);
                float p11 = ex2(s[nb][3]);
                if (maskMode == 1) {
                    if ((unsigned)(c     - (rA - PRE)) > 2u*PRE) p00 = 0.f;
                    if ((unsigned)(c + 1 - (rA - PRE)) > 2u*PRE) p01 = 0.f;
                    if ((unsigned)(c     - (rB - PRE)) > 2u*PRE) p10 = 0.f;
                    if ((unsigned)(c + 1 - (rB - PRE)) > 2u*PRE) p11 = 0.f;
                } else if (maskMode == 2) {
                    if (c     >= S_TOT) { p00 = 0.f; p10 = 0.f; }
                    if (c + 1 >= S_TOT) { p01 = 0.f; p11 = 0.f; }
                }
                ph[nb][0] = pack2(p00, p01);
                ph[nb][1] = pack2(p10, p11);
            }

            // ---- PV: O += P * Vh ; lacc += P * ones ----
#pragma unroll
            for (int kc = 0; kc < 4; kc++) {
                u32 Ah[4] = { ph[2*kc][0], ph[2*kc][1], ph[2*kc+1][0], ph[2*kc+1][1] };
                mma(laccF, Ah, ONES16, ONES16);     // row sums (free l accumulation)
#pragma unroll
                for (int nb2 = 0; nb2 < 8; nb2++) {
                    u32 Bh[4];
                    ldsm4t(Bh, kvb + offBV + hof + kc * (16 * RSTR) + nb2 * 32);
                    mma(o[2*nb2],   Ah, Bh[0], Bh[1]);
                    mma(o[2*nb2+1], Ah, Bh[2], Bh[3]);
                }
            }
        }
    }

    // ---- finalize (laccF[0]/[2] are complete row sums; no reduction needed) ----
    const float laccA = laccF[0], laccB = laccF[2];

    if (chunk < 0) {
        float invA = 1.f / laccA, invB = 1.f / laccB;
        if (rA < S_TOT) {
            float* base = O + ((size_t)orig_idx(rA) * NH + head) * HD;
#pragma unroll
            for (int nb = 0; nb < 16; nb++)
                *(float2*)(base + nb * 8 + 2 * tg) = make_float2(o[nb][0] * invA, o[nb][1] * invA);
        }
        if (rB < S_TOT) {
            float* base = O + ((size_t)orig_idx(rB) * NH + head) * HD;
#pragma unroll
            for (int nb = 0; nb < 16; nb++)
                *(float2*)(base + nb * 8 + 2 * tg) = make_float2(o[nb][2] * invB, o[nb][3] * invB);
        }
    } else {
        float* so = g_scrO + (size_t)eidx * 16384;
        int rlA = w * 16 + g, rlB = rlA + 8;
#pragma unroll
        for (int nb = 0; nb < 16; nb++) {
            *(float2*)(so + rlA * 128 + nb * 8 + 2 * tg) = make_float2(o[nb][0], o[nb][1]);
            *(float2*)(so + rlB * 128 + nb * 8 + 2 * tg) = make_float2(o[nb][2], o[nb][3]);
        }
        if (tg == 0) {
            g_scrL[eidx * 128 + rlA] = laccA;
            g_scrL[eidx * 128 + rlB] = laccB;
        }
    }
}

// ---------------- combine tail partials (wide grid) ----------------
__global__ __launch_bounds__(256) void combine_kernel(float* __restrict__ O) {
    int pair  = blockIdx.x >> 4;
    int slice = blockIdx.x & 15;
    int tileIdx = pair >> 1, head = pair & 1;
    int tile = 65 + tileIdx, r0 = tile * 128;
    int ebase = tileIdx * 16 + head * 8;
    int tid = threadIdx.x;

    __shared__ float ls[8];
    if (tid < 8) {
        int row = slice * 8 + tid;
        float sum = 0.f;
#pragma unroll
        for (int c = 0; c < NCHUNK; c++) sum += g_scrL[(ebase + c) * 128 + row];
        ls[tid] = 1.f / sum;
    }
    __syncthreads();

#pragma unroll
    for (int r = 0; r < 4; r++) {
        int k = slice * 1024 + r * 256 + tid;
        int row = k >> 7, col = k & 127;
        if (r0 + row >= S_TOT) continue;
        float sum = 0.f;
#pragma unroll
        for (int c = 0; c < NCHUNK; c++) sum += g_scrO[(size_t)(ebase + c) * 16384 + k];
        int gr = orig_idx(r0 + row);
        O[((size_t)gr * NH + head) * HD + col] = sum * ls[row - slice * 8];
    }
}

// ---------------- launch ----------------
extern "C" void kernel_launch(void* const* d_in, const int* in_sizes, int n_in,
                              void* d_out, int out_size)
{
    const float* Q = (const float*)d_in[0];
    const float* K = (const float*)d_in[1];
    const float* V = (const float*)d_in[2];
    float* O     = (float*)d_out;
    float* ratio = O + (size_t)S_TOT * NH * HD;

    cudaFuncSetAttribute(fused_kernel, cudaFuncAttributeMaxDynamicSharedMemorySize, SMEM_ATTN);

    prep_qkv<<<dim3(1202, NH), 256>>>(Q, K, V, ratio);
    fused_kernel<<<342, 256, SMEM_ATTN>>>(O, ratio);
    combine_kernel<<<352, 256>>>(O);
}

// round 12
// speedup vs baseline: 16.1821x; 1.0593x over previous
#include <cuda_runtime.h>
#include <cuda_fp16.h>
#include <math.h>

typedef unsigned int u32;

// ---------------- problem constants ----------------
#define S_TOT 9616
#define RAZOR 8320
#define PF    1040
#define ROT   8576
#define NH    2
#define HD    128
#define PRE   2048
#define WIN   301
// SCALE * log2(e), absorbed into Q at prep; scores exponentiated with ex2
#define QSCALE 0.12751741522f
#define ONES16 0x3C003C00u     // fp16 {1.0, 1.0}

// rotated fp16 buffers [h][s][d]  (Q pre-scaled by QSCALE)
__device__ __half g_Qh[(size_t)NH*S_TOT*HD];
__device__ __half g_Kh[(size_t)NH*S_TOT*HD];
__device__ __half g_Vh[(size_t)NH*S_TOT*HD];

// tail-tile partial scratch: 11 tiles x 2 heads x 8 chunks
#define NCHUNK 8
__device__ float g_scrO[(size_t)11*2*NCHUNK*128*128];
__device__ float g_scrL[(size_t)11*2*NCHUNK*128];

__device__ __forceinline__ int orig_idx(int r) { return r < ROT ? r + PF : r - ROT; }

__device__ __forceinline__ u32 smem_u32(const void* p) {
    u32 a;
    asm("{ .reg .u64 t; cvta.to.shared.u64 t, %1; cvt.u32.u64 %0, t; }" : "=r"(a) : "l"(p));
    return a;
}
__device__ __forceinline__ void ldsm4(u32* r, u32 a) {
    asm volatile("ldmatrix.sync.aligned.m8n8.x4.shared.b16 {%0,%1,%2,%3}, [%4];"
                 : "=r"(r[0]), "=r"(r[1]), "=r"(r[2]), "=r"(r[3]) : "r"(a));
}
__device__ __forceinline__ void ldsm4t(u32* r, u32 a) {
    asm volatile("ldmatrix.sync.aligned.m8n8.x4.trans.shared.b16 {%0,%1,%2,%3}, [%4];"
                 : "=r"(r[0]), "=r"(r[1]), "=r"(r[2]), "=r"(r[3]) : "r"(a));
}
__device__ __forceinline__ void mma(float* d, const u32* a, u32 b0, u32 b1) {
    asm volatile("mma.sync.aligned.m16n8k16.row.col.f32.f16.f16.f32 "
                 "{%0,%1,%2,%3},{%4,%5,%6,%7},{%8,%9},{%0,%1,%2,%3};"
                 : "+f"(d[0]), "+f"(d[1]), "+f"(d[2]), "+f"(d[3])
                 : "r"(a[0]), "r"(a[1]), "r"(a[2]), "r"(a[3]), "r"(b0), "r"(b1));
}
__device__ __forceinline__ u32 pack2(float a, float b) {
    __half2 t = __floats2half2_rn(a, b);
    return *(u32*)&t;
}
__device__ __forceinline__ float ex2(float x) {
    float r;
    asm("ex2.approx.ftz.f32 %0, %1;" : "=f"(r) : "f"(x));
    return r;
}

#define CP_ASYNC16(d, s) asm volatile("cp.async.cg.shared.global [%0], [%1], 16;" :: "r"(d), "l"(s))
#define CP_COMMIT()      asm volatile("cp.async.commit_group;" ::: "memory")
#define CP_WAIT1()       asm volatile("cp.async.wait_group 1;" ::: "memory")

// ---------------- smem layout ----------------
#define RSTR 272
#define KROWS (128*RSTR)               // 34816: 128 rows (K or V)
#define KVBUF (2*KROWS)                // 69632: [KH(128r) | VH(128r)]
#define NSTG  3
#define SMEM_ATTN (NSTG*KVBUF)         // 208896

// ---------------- prep: rotate + fp16 convert (Q pre-scaled) + zero ratio ----------------
__global__ __launch_bounds__(256) void prep_qkv(const float* __restrict__ Q,
                                                const float* __restrict__ K,
                                                const float* __restrict__ V,
                                                float* __restrict__ ratio) {
    if (blockIdx.x == 0 && blockIdx.y == 0 && threadIdx.x < 4) ratio[threadIdx.x] = 0.f;
    int h = blockIdx.y;
    int s = blockIdx.x * 8 + (threadIdx.x >> 5);
    if (s >= S_TOT) return;
    int lane = threadIdx.x & 31;
    int gq = orig_idx(s);
    size_t si = ((size_t)gq * NH + h) * HD + lane * 4;
    size_t o  = ((size_t)h * S_TOT + s) * HD + lane * 4;
    float4 qv = *(const float4*)(Q + si);
    float4 kv = *(const float4*)(K + si);
    float4 vv = *(const float4*)(V + si);
    *(uint2*)(g_Qh + o) = make_uint2(pack2(qv.x * QSCALE, qv.y * QSCALE),
                                     pack2(qv.z * QSCALE, qv.w * QSCALE));
    *(uint2*)(g_Kh + o) = make_uint2(pack2(kv.x, kv.y), pack2(kv.z, kv.w));
    *(uint2*)(g_Vh + o) = make_uint2(pack2(vv.x, vv.y), pack2(vv.z, vv.w));
}

// ---------------- async KV block load: 128 rows of K and V ----------------
__device__ __forceinline__ void kv_load(u32 kvb, int c0, int tid,
    const __half* kh, const __half* vh)
{
#pragma unroll
    for (int it = 0; it < 8; it++) {
        int idx = tid + it * 256;            // 0..2047
        int row = idx >> 4, ch = idx & 15;
        size_t src = (size_t)min(c0 + row, S_TOT - 1) * HD + ch * 8;
        u32 dst = kvb + row * RSTR + ch * 16;
        CP_ASYNC16(dst,         kh + src);
        CP_ASYNC16(dst + KROWS, vh + src);
    }
}

// ---------------- fused attention + ratio kernel ----------------
__global__ __launch_bounds__(256, 1)
void fused_kernel(float* __restrict__ O, float* __restrict__ ratio)
{
    extern __shared__ char sm[];
    const u32 sb  = smem_u32(sm);
    const int tid = threadIdx.x, w = tid >> 5, lane = tid & 31;
    const int g = lane >> 2, tg = lane & 3;

    if (blockIdx.x >= 306) {
        // ================= ratio path (fp16 QK, Q frags in registers) =================
        int e = blockIdx.x - 306;            // 0..35
        const int type = e / 18, head = (e / 9) & 1, rb = e % 9;
        const int r0 = rb * 128;
        const int stride = type ? 8 : 1;

        const __half* qh = g_Qh + (size_t)head * S_TOT * HD;
        const __half* kh = g_Kh + (size_t)head * S_TOT * HD;

        // Q fragments direct from global (A-frag layout)
        u32 qf[8][4];
        {
            const int rqa = min(r0 + w * 16 + g,     PF - 1) * stride;
            const int rqb = min(r0 + w * 16 + g + 8, PF - 1) * stride;
#pragma unroll
            for (int kc = 0; kc < 8; kc++) {
                int d = kc * 16 + 2 * tg;
                qf[kc][0] = *(const u32*)(qh + (size_t)rqa * HD + d);
                qf[kc][1] = *(const u32*)(qh + (size_t)rqb * HD + d);
                qf[kc][2] = *(const u32*)(qh + (size_t)rqa * HD + d + 8);
                qf[kc][3] = *(const u32*)(qh + (size_t)rqb * HD + d + 8);
            }
        }

        const u32 bAddr = sb + ((lane & 7) + ((lane >> 4) & 1) * 8) * RSTR
                        + ((lane >> 3) & 1) * 16;

        float totA = 0.f, winA = 0.f, totB = 0.f, winB = 0.f;
        const int rA = r0 + w * 16 + g, rB = rA + 8;

        for (int blk = 0; blk < 17; blk++) {
            const int c0 = blk * 64;
            __syncthreads();
#pragma unroll
            for (int it = 0; it < 4; it++) {
                int idx = tid + it * 256;
                int row = idx >> 4, ch = idx & 15;
                size_t src = (size_t)(min(c0 + row, PF - 1) * stride) * HD + ch * 8;
                *(uint4*)(sm + row * RSTR + ch * 16) = *(const uint4*)(kh + src);
            }
            __syncthreads();

            float s[8][4];
#pragma unroll
            for (int x = 0; x < 8; x++)
#pragma unroll
                for (int j = 0; j < 4; j++) s[x][j] = 0.f;
#pragma unroll
            for (int kc = 0; kc < 8; kc++) {
#pragma unroll
                for (int nb2 = 0; nb2 < 4; nb2++) {
                    u32 Bh[4];
                    ldsm4(Bh, bAddr + nb2 * (16 * RSTR) + kc * 32);
                    mma(s[2*nb2],   qf[kc], Bh[0], Bh[1]);
                    mma(s[2*nb2+1], qf[kc], Bh[2], Bh[3]);
                }
            }
#pragma unroll
            for (int nb = 0; nb < 8; nb++) {
                int c = c0 + nb * 8 + 2 * tg;
#pragma unroll
                for (int v = 0; v < 4; v++) {
                    int cc = c + (v & 1);
                    int rr = (v < 2) ? rA : rB;
                    float p = (cc < PF) ? ex2(s[nb][v]) : 0.f;
                    if (v < 2) { totA += p; if (abs(rr - cc) <= WIN) winA += p; }
                    else       { totB += p; if (abs(rr - cc) <= WIN) winB += p; }
                }
            }
        }

        totA += __shfl_xor_sync(0xffffffffu, totA, 1);
        totA += __shfl_xor_sync(0xffffffffu, totA, 2);
        winA += __shfl_xor_sync(0xffffffffu, winA, 1);
        winA += __shfl_xor_sync(0xffffffffu, winA, 2);
        totB += __shfl_xor_sync(0xffffffffu, totB, 1);
        totB += __shfl_xor_sync(0xffffffffu, totB, 2);
        winB += __shfl_xor_sync(0xffffffffu, winB, 1);
        winB += __shfl_xor_sync(0xffffffffu, winB, 2);

        float* red = (float*)sm;
        __syncthreads();
        if (tid == 0) red[0] = 0.f;
        __syncthreads();
        if (tg == 0) {
            float contrib = 0.f;
            if (rA < PF) contrib += winA / totA;
            if (rB < PF) contrib += winB / totB;
            if (contrib != 0.f) atomicAdd(red, contrib);
        }
        __syncthreads();
        if (tid == 0) atomicAdd(&ratio[type * NH + head], red[0] * (1.f / (float)PF));
        return;
    }

    // ================= attention path (128-col big-iters, 3-stage pipeline) =================
    int tile, head, chunk = -1, eidx = 0;
    int lo0, hi0, lo1, hi1;
    if (blockIdx.x < 130) {
        tile = blockIdx.x >> 1; head = blockIdx.x & 1;
        lo0 = max(0, tile - 16); hi0 = min(64, tile + 16);   // band, 128-blocks
        lo1 = 65; hi1 = 75;                                   // tail
    } else {
        int e = blockIdx.x - 130;
        int tileIdx = e >> 4; head = (e >> 3) & 1; chunk = e & 7;
        tile = 65 + tileIdx;
        eidx = e;
        lo0 = (76 * chunk) / 8; hi0 = (76 * (chunk + 1)) / 8 - 1;
        lo1 = 0; hi1 = -1;
    }
    const int r0 = tile * 128;
    const bool rowRazor = (tile < 65);
    const int n0 = hi0 - lo0 + 1;
    const int nb_total = n0 + (hi1 >= lo1 ? hi1 - lo1 + 1 : 0);

    const __half* qh = g_Qh + (size_t)head * S_TOT * HD;
    const __half* kh = g_Kh + (size_t)head * S_TOT * HD;
    const __half* vh = g_Vh + (size_t)head * S_TOT * HD;

#define BLK_OF(j) (((j) < n0) ? lo0 + (j) : lo1 + ((j) - n0))

    // prologue: issue loads for big-iters 0 and 1
    kv_load(sb,         BLK_OF(0) * 128, tid, kh, vh);
    CP_COMMIT();
    kv_load(sb + KVBUF, BLK_OF(min(1, nb_total - 1)) * 128, tid, kh, vh);
    CP_COMMIT();

    // Q fragments direct from global (A-frag layout), held for entire kernel
    u32 qf[8][4];
    {
        const int rqa = min(r0 + w * 16 + g,     S_TOT - 1);
        const int rqb = min(r0 + w * 16 + g + 8, S_TOT - 1);
#pragma unroll
        for (int kc = 0; kc < 8; kc++) {
            int d = kc * 16 + 2 * tg;
            qf[kc][0] = *(const u32*)(qh + (size_t)rqa * HD + d);
            qf[kc][1] = *(const u32*)(qh + (size_t)rqb * HD + d);
            qf[kc][2] = *(const u32*)(qh + (size_t)rqa * HD + d + 8);
            qf[kc][3] = *(const u32*)(qh + (size_t)rqb * HD + d + 8);
        }
    }

    const u32 offBK = ((lane & 7) + ((lane >> 4) & 1) * 8) * RSTR + ((lane >> 3) & 1) * 16;
    const u32 offBV = KROWS + ((lane & 7) + ((lane >> 3) & 1) * 8) * RSTR + ((lane >> 4) & 1) * 16;

    float o[16][4];
#pragma unroll
    for (int i = 0; i < 16; i++)
#pragma unroll
        for (int j = 0; j < 4; j++) o[i][j] = 0.f;
    float laccF[4] = {0.f, 0.f, 0.f, 0.f};      // row sums via ones-MMA
    const int rA = r0 + w * 16 + g, rB = rA + 8;
    const int t2lo = 2 * tile - 30, t2hi = 2 * tile + 31;

    int st = 0;                                   // stage being consumed
    for (int i = 0; i < nb_total; i++) {
        const int blk = BLK_OF(i);

        CP_WAIT1();            // iter i's group complete (<=1 outstanding)
        __syncthreads();       // CTA-wide visibility; all warps past iter i-1
        {
            int nxt = i + 2;
            if (nxt < nb_total) {
                int ns = st + 2; if (ns >= NSTG) ns -= NSTG;   // stage freed at i-1
                kv_load(sb + ns * KVBUF, BLK_OF(nxt) * 128, tid, kh, vh);
            }
            CP_COMMIT();       // uniform group counting
        }
        const u32 kvb = sb + st * KVBUF;
        if (++st == NSTG) st = 0;

#pragma unroll
        for (int h = 0; h < 2; h++) {
            const int sub = 2 * blk + h;          // 64-col sub-block index
            if (sub == 151) continue;             // beyond sequence entirely
            const int c0 = sub * 64;
            int maskMode = 0;
            if (sub < 130) { if (rowRazor && (sub < t2lo || sub > t2hi)) maskMode = 1; }
            else if (sub == 150) maskMode = 2;
            const u32 hof = h * (64 * RSTR);

            // ---- QK: S = Qh * Kh ----
            float s[8][4];
#pragma unroll
            for (int x = 0; x < 8; x++)
#pragma unroll
                for (int j = 0; j < 4; j++) s[x][j] = 0.f;

#pragma unroll
            for (int kc = 0; kc < 8; kc++) {
#pragma unroll
                for (int nb2 = 0; nb2 < 4; nb2++) {
                    u32 Bh[4];
                    ldsm4(Bh, kvb + offBK + hof + nb2 * (16 * RSTR) + kc * 32);
                    mma(s[2*nb2],   qf[kc], Bh[0], Bh[1]);
                    mma(s[2*nb2+1], qf[kc], Bh[2], Bh[3]);
                }
            }

            // ---- epilogue: mask + ex2 + fp16 pack ----
            u32 ph[8][2];
#pragma unroll
            for (int nb = 0; nb < 8; nb++) {
                int c = c0 + nb * 8 + 2 * tg;
                float p00 = ex2(s[nb][0]);
                float p01 = ex2(s[nb][1]);
                float p10 = ex2(s[nb][2]);
                float p11 = ex2(s[nb][3]);
                if (maskMode == 1) {
                    if ((unsigned)(c     - (rA - PRE)) > 2u*PRE) p00 = 0.f;
                    if ((unsigned)(c + 1 - (rA - PRE)) > 2u*PRE) p01 = 0.f;
                    if ((unsigned)(c     - (rB - PRE)) > 2u*PRE) p10 = 0.f;
                    if ((unsigned)(c + 1 - (rB - PRE)) > 2u*PRE) p11 = 0.f;
                } else if (maskMode == 2) {
                    if (c     >= S_TOT) { p00 = 0.f; p10 = 0.f; }
                    if (c + 1 >= S_TOT) { p01 = 0.f; p11 = 0.f; }
                }
                ph[nb][0] = pack2(p00, p01);
                ph[nb][1] = pack2(p10, p11);
            }

            // ---- PV: O += P * Vh ; lacc += P * ones ----
#pragma unroll
            for (int kc = 0; kc < 4; kc++) {
                u32 Ah[4] = { ph[2*kc][0], ph[2*kc][1], ph[2*kc+1][0], ph[2*kc+1][1] };
                mma(laccF, Ah, ONES16, ONES16);     // row sums (free l accumulation)
#pragma unroll
                for (int nb2 = 0; nb2 < 8; nb2++) {
                    u32 Bh[4];
                    ldsm4t(Bh, kvb + offBV + hof + kc * (16 * RSTR) + nb2 * 32);
                    mma(o[2*nb2],   Ah, Bh[0], Bh[1]);
                    mma(o[2*nb2+1], Ah, Bh[2], Bh[3]);
                }
            }
        }
    }

    // ---- finalize (laccF[0]/[2] are complete row sums) ----
    const float laccA = laccF[0], laccB = laccF[2];

    if (chunk < 0) {
        float invA = 1.f / laccA, invB = 1.f / laccB;
        if (rA < S_TOT) {
            float* base = O + ((size_t)orig_idx(rA) * NH + head) * HD;
#pragma unroll
            for (int nb = 0; nb < 16; nb++)
                *(float2*)(base + nb * 8 + 2 * tg) = make_float2(o[nb][0] * invA, o[nb][1] * invA);
        }
        if (rB < S_TOT) {
            float* base = O + ((size_t)orig_idx(rB) * NH + head) * HD;
#pragma unroll
            for (int nb = 0; nb < 16; nb++)
                *(float2*)(base + nb * 8 + 2 * tg) = make_float2(o[nb][2] * invB, o[nb][3] * invB);
        }
    } else {
        float* so = g_scrO + (size_t)eidx * 16384;
        int rlA = w * 16 + g, rlB = rlA + 8;
#pragma unroll
        for (int nb = 0; nb < 16; nb++) {
            *(float2*)(so + rlA * 128 + nb * 8 + 2 * tg) = make_float2(o[nb][0], o[nb][1]);
            *(float2*)(so + rlB * 128 + nb * 8 + 2 * tg) = make_float2(o[nb][2], o[nb][3]);
        }
        if (tg == 0) {
            g_scrL[eidx * 128 + rlA] = laccA;
            g_scrL[eidx * 128 + rlB] = laccB;
        }
    }
}

// ---------------- combine tail partials (wide grid) ----------------
__global__ __launch_bounds__(256) void combine_kernel(float* __restrict__ O) {
    int pair  = blockIdx.x >> 4;
    int slice = blockIdx.x & 15;
    int tileIdx = pair >> 1, head = pair & 1;
    int tile = 65 + tileIdx, r0 = tile * 128;
    int ebase = tileIdx * 16 + head * 8;
    int tid = threadIdx.x;

    __shared__ float ls[8];
    if (tid < 8) {
        int row = slice * 8 + tid;
        float sum = 0.f;
#pragma unroll
        for (int c = 0; c < NCHUNK; c++) sum += g_scrL[(ebase + c) * 128 + row];
        ls[tid] = 1.f / sum;
    }
    __syncthreads();

#pragma unroll
    for (int r = 0; r < 4; r++) {
        int k = slice * 1024 + r * 256 + tid;
        int row = k >> 7, col = k & 127;
        if (r0 + row >= S_TOT) continue;
        float sum = 0.f;
#pragma unroll
        for (int c = 0; c < NCHUNK; c++) sum += g_scrO[(size_t)(ebase + c) * 16384 + k];
        int gr = orig_idx(r0 + row);
        O[((size_t)gr * NH + head) * HD + col] = sum * ls[row - slice * 8];
    }
}

// ---------------- launch ----------------
extern "C" void kernel_launch(void* const* d_in, const int* in_sizes, int n_in,
                              void* d_out, int out_size)
{
    const float* Q = (const float*)d_in[0];
    const float* K = (const float*)d_in[1];
    const float* V = (const float*)d_in[2];
    float* O     = (float*)d_out;
    float* ratio = O + (size_t)S_TOT * NH * HD;

    cudaFuncSetAttribute(fused_kernel, cudaFuncAttributeMaxDynamicSharedMemorySize, SMEM_ATTN);

    prep_qkv<<<dim3(1202, NH), 256>>>(Q, K, V, ratio);
    fused_kernel<<<342, 256, SMEM_ATTN>>>(O, ratio);
    combine_kernel<<<352, 256>>>(O);
}